// round 1
// baseline (speedup 1.0000x reference)
#include <cuda_runtime.h>
#include <cuda_bf16.h>
#include <math.h>

// ---------------- problem constants ----------------
#define BATCH 8
#define SEQ   1024
#define DMODEL 1024
#define NHEAD 16
#define HDIM  64
#define FFDIM 4096
#define NTOK  (BATCH * SEQ)          // 8192

// ---------------- scratch (device globals, no allocation) ----------------
__device__ float g_h      [(long)NTOK * DMODEL];      // ln1 out
__device__ float g_qkv    [(long)NTOK * 3 * DMODEL];  // qkv
__device__ float g_scores [(long)BATCH * NHEAD * SEQ * SEQ]; // 512 MB
__device__ float g_ctx    [(long)NTOK * DMODEL];
__device__ float g_attnout[(long)NTOK * DMODEL];      // residual1 output (skip)
__device__ float g_h2     [(long)NTOK * DMODEL];      // ln2 out
__device__ float g_ff1    [(long)NTOK * FFDIM];

// ---------------- block reductions (256 threads) ----------------
__device__ __forceinline__ float blockReduceSum(float v, float* sbuf) {
    #pragma unroll
    for (int o = 16; o > 0; o >>= 1) v += __shfl_xor_sync(0xffffffffu, v, o);
    const int w = threadIdx.x >> 5;
    if ((threadIdx.x & 31) == 0) sbuf[w] = v;
    __syncthreads();
    if (threadIdx.x < 32) {
        float t = (threadIdx.x < 8) ? sbuf[threadIdx.x] : 0.0f;
        #pragma unroll
        for (int o = 4; o > 0; o >>= 1) t += __shfl_xor_sync(0xffffffffu, t, o);
        if (threadIdx.x == 0) sbuf[0] = t;
    }
    __syncthreads();
    float r = sbuf[0];
    __syncthreads();
    return r;
}

__device__ __forceinline__ float blockReduceMax(float v, float* sbuf) {
    #pragma unroll
    for (int o = 16; o > 0; o >>= 1) v = fmaxf(v, __shfl_xor_sync(0xffffffffu, v, o));
    const int w = threadIdx.x >> 5;
    if ((threadIdx.x & 31) == 0) sbuf[w] = v;
    __syncthreads();
    if (threadIdx.x < 32) {
        float t = (threadIdx.x < 8) ? sbuf[threadIdx.x] : -3.4e38f;
        #pragma unroll
        for (int o = 4; o > 0; o >>= 1) t = fmaxf(t, __shfl_xor_sync(0xffffffffu, t, o));
        if (threadIdx.x == 0) sbuf[0] = t;
    }
    __syncthreads();
    float r = sbuf[0];
    __syncthreads();
    return r;
}

// ---------------- layernorm: one block per token, 256 threads ----------------
__global__ void layernorm_kernel(const float* __restrict__ x, const float* __restrict__ g,
                                 const float* __restrict__ b, float* __restrict__ out) {
    __shared__ float sbuf[8];
    const long row = blockIdx.x;
    const int tid = threadIdx.x;
    const float4 xv = reinterpret_cast<const float4*>(x + row * DMODEL)[tid];
    float s = xv.x + xv.y + xv.z + xv.w;
    s = blockReduceSum(s, sbuf);
    const float mu = s * (1.0f / (float)DMODEL);
    const float dx = xv.x - mu, dy = xv.y - mu, dz = xv.z - mu, dw = xv.w - mu;
    float vs = dx*dx + dy*dy + dz*dz + dw*dw;
    vs = blockReduceSum(vs, sbuf);
    const float inv = rsqrtf(vs * (1.0f / (float)DMODEL) + 1e-5f);
    const float4 gv = reinterpret_cast<const float4*>(g)[tid];
    const float4 bv = reinterpret_cast<const float4*>(b)[tid];
    float4 o;
    o.x = dx * inv * gv.x + bv.x;
    o.y = dy * inv * gv.y + bv.y;
    o.z = dz * inv * gv.z + bv.z;
    o.w = dw * inv * gv.w + bv.w;
    reinterpret_cast<float4*>(out + row * DMODEL)[tid] = o;
}

// ---------------- softmax over last dim (1024), scale 1/sqrt(HD) ----------------
__global__ void softmax_kernel(float* __restrict__ s) {
    __shared__ float sbuf[8];
    const long row = blockIdx.x;
    float4* p = reinterpret_cast<float4*>(s) + row * (SEQ / 4) + threadIdx.x;
    float4 v = *p;
    const float sc = 0.125f;  // 1/sqrt(64)
    v.x *= sc; v.y *= sc; v.z *= sc; v.w *= sc;
    float m = fmaxf(fmaxf(v.x, v.y), fmaxf(v.z, v.w));
    m = blockReduceMax(m, sbuf);
    v.x = __expf(v.x - m); v.y = __expf(v.y - m);
    v.z = __expf(v.z - m); v.w = __expf(v.w - m);
    float ss = v.x + v.y + v.z + v.w;
    ss = blockReduceSum(ss, sbuf);
    const float inv = 1.0f / ss;
    v.x *= inv; v.y *= inv; v.z *= inv; v.w *= inv;
    *p = v;
}

// ---------------- generic tiled SGEMM ----------------
// out[m,n] = sum_k A[m,k] * (BT ? B[n,k] : B[k,n])  (+bias)(gelu)(+res)
// per-z base offsets: off(z) = (z>>4)*s1 + (z&15)*s2   (covers linear & (b,h) batching)
// All dims assumed multiples of the tile (true for this problem).
__device__ __forceinline__ float gelu_exact(float v) {
    return 0.5f * v * (1.0f + erff(v * 0.70710678118654752f));
}

template<bool BT, bool HAS_BIAS, bool GELU, bool HAS_RES>
__global__ void __launch_bounds__(256, 4)
gemm_kernel(const float* __restrict__ A, const float* __restrict__ B,
            const float* __restrict__ bias, const float* __restrict__ res,
            float* __restrict__ out,
            int K, int lda, int ldb, int ldo,
            long sA1, long sA2, long sB1, long sB2, long sO1, long sO2)
{
    const int z = blockIdx.z;
    A   += (long)(z >> 4) * sA1 + (long)(z & 15) * sA2;
    B   += (long)(z >> 4) * sB1 + (long)(z & 15) * sB2;
    out += (long)(z >> 4) * sO1 + (long)(z & 15) * sO2;
    if (HAS_RES) res += (long)(z >> 4) * sO1 + (long)(z & 15) * sO2;

    __shared__ float As[16][68];
    __shared__ float Bs[16][68];

    const int tid = threadIdx.x;
    const int tx = tid & 15, ty = tid >> 4;
    const int row0 = blockIdx.y * 64;
    const int col0 = blockIdx.x * 64;

    float acc[4][4] = {};

    for (int k0 = 0; k0 < K; k0 += 16) {
        {   // A tile: 64 rows x 16 k, stored transposed
            const int r = tid >> 2, c = (tid & 3) * 4;
            const float4 a = *reinterpret_cast<const float4*>(A + (long)(row0 + r) * lda + k0 + c);
            As[c+0][r] = a.x; As[c+1][r] = a.y; As[c+2][r] = a.z; As[c+3][r] = a.w;
        }
        if (BT) {   // B tile from B[n,k]: 64 n-rows x 16 k
            const int r = tid >> 2, c = (tid & 3) * 4;
            const float4 bv = *reinterpret_cast<const float4*>(B + (long)(col0 + r) * ldb + k0 + c);
            Bs[c+0][r] = bv.x; Bs[c+1][r] = bv.y; Bs[c+2][r] = bv.z; Bs[c+3][r] = bv.w;
        } else {    // B tile from B[k,n]: 16 k-rows x 64 n
            const int r = tid >> 4, c = (tid & 15) * 4;
            const float4 bv = *reinterpret_cast<const float4*>(B + (long)(k0 + r) * ldb + col0 + c);
            Bs[r][c+0] = bv.x; Bs[r][c+1] = bv.y; Bs[r][c+2] = bv.z; Bs[r][c+3] = bv.w;
        }
        __syncthreads();
        #pragma unroll
        for (int kc = 0; kc < 16; kc++) {
            float ra[4], rb[4];
            #pragma unroll
            for (int i = 0; i < 4; i++) ra[i] = As[kc][ty * 4 + i];
            #pragma unroll
            for (int j = 0; j < 4; j++) rb[j] = Bs[kc][tx * 4 + j];
            #pragma unroll
            for (int i = 0; i < 4; i++)
                #pragma unroll
                for (int j = 0; j < 4; j++)
                    acc[i][j] = fmaf(ra[i], rb[j], acc[i][j]);
        }
        __syncthreads();
    }

    #pragma unroll
    for (int i = 0; i < 4; i++) {
        const int r = row0 + ty * 4 + i;
        #pragma unroll
        for (int j = 0; j < 4; j++) {
            const int c = col0 + tx * 4 + j;
            float v = acc[i][j];
            if (HAS_BIAS) v += bias[c];
            if (GELU)     v = gelu_exact(v);
            if (HAS_RES)  v += res[(long)r * ldo + c];
            out[(long)r * ldo + c] = v;
        }
    }
}

// ---------------- host launcher ----------------
extern "C" void kernel_launch(void* const* d_in, const int* in_sizes, int n_in,
                              void* d_out, int out_size) {
    const float* x      = (const float*)d_in[0];
    const float* ln1_g  = (const float*)d_in[1];
    const float* ln1_b  = (const float*)d_in[2];
    const float* ln2_g  = (const float*)d_in[3];
    const float* ln2_b  = (const float*)d_in[4];
    const float* W_qkv  = (const float*)d_in[5];
    const float* b_qkv  = (const float*)d_in[6];
    const float* W_proj = (const float*)d_in[7];
    const float* b_proj = (const float*)d_in[8];
    const float* W1     = (const float*)d_in[9];
    const float* b1     = (const float*)d_in[10];
    const float* W2     = (const float*)d_in[11];
    const float* b2     = (const float*)d_in[12];
    float* out = (float*)d_out;

    float *h, *qkv, *scores, *ctx, *attnout, *h2, *ff1;
    cudaGetSymbolAddress((void**)&h,       g_h);
    cudaGetSymbolAddress((void**)&qkv,     g_qkv);
    cudaGetSymbolAddress((void**)&scores,  g_scores);
    cudaGetSymbolAddress((void**)&ctx,     g_ctx);
    cudaGetSymbolAddress((void**)&attnout, g_attnout);
    cudaGetSymbolAddress((void**)&h2,      g_h2);
    cudaGetSymbolAddress((void**)&ff1,     g_ff1);

    const long QKV_B = (long)SEQ * 3 * DMODEL;     // per-batch stride inside packed qkv
    const long SC_Z  = (long)SEQ * SEQ;            // per-(b,h) stride in scores
    const long CTX_B = (long)SEQ * DMODEL;         // per-batch stride in ctx

    // 1. LN1
    layernorm_kernel<<<NTOK, 256>>>(x, ln1_g, ln1_b, h);

    // 2. qkv = h @ W_qkv^T + b_qkv          [8192 x 3072]
    gemm_kernel<true, true, false, false><<<dim3(3 * DMODEL / 64, NTOK / 64, 1), 256>>>(
        h, W_qkv, b_qkv, nullptr, qkv,
        DMODEL, DMODEL, DMODEL, 3 * DMODEL,
        0, 0, 0, 0, 0, 0);

    // 3. scores = Q @ K^T  (batched over 128 (b,h) pairs), K=64
    gemm_kernel<true, false, false, false><<<dim3(SEQ / 64, SEQ / 64, BATCH * NHEAD), 256>>>(
        qkv /*Q*/, qkv + DMODEL /*K*/, nullptr, nullptr, scores,
        HDIM, 3 * DMODEL, 3 * DMODEL, SEQ,
        QKV_B, HDIM,          // A offsets: b*QKV_B + h*64
        QKV_B, HDIM,          // B offsets
        16 * SC_Z, SC_Z);     // O offsets: linear z*SC_Z

    // 4. softmax (scale 1/8 inside)
    softmax_kernel<<<BATCH * NHEAD * SEQ, 256>>>(scores);

    // 5. ctx = attn @ V  (batched), B accessed as B[k,n]
    gemm_kernel<false, false, false, false><<<dim3(HDIM / 64, SEQ / 64, BATCH * NHEAD), 256>>>(
        scores, qkv + 2 * DMODEL /*V*/, nullptr, nullptr, ctx,
        SEQ, SEQ, 3 * DMODEL, DMODEL,
        16 * SC_Z, SC_Z,      // A: linear z*SC_Z
        QKV_B, HDIM,          // B: b*QKV_B + h*64
        CTX_B, HDIM);         // O: b*CTX_B + h*64

    // 6. attnout = ctx @ W_proj^T + b_proj + x   (residual 1)
    gemm_kernel<true, true, false, true><<<dim3(DMODEL / 64, NTOK / 64, 1), 256>>>(
        ctx, W_proj, b_proj, x, attnout,
        DMODEL, DMODEL, DMODEL, DMODEL,
        0, 0, 0, 0, 0, 0);

    // 7. LN2
    layernorm_kernel<<<NTOK, 256>>>(attnout, ln2_g, ln2_b, h2);

    // 8. ff1 = gelu(h2 @ W1^T + b1)          [8192 x 4096]
    gemm_kernel<true, true, true, false><<<dim3(FFDIM / 64, NTOK / 64, 1), 256>>>(
        h2, W1, b1, nullptr, ff1,
        DMODEL, DMODEL, DMODEL, FFDIM,
        0, 0, 0, 0, 0, 0);

    // 9. out = gelu(ff1 @ W2^T + b2) + attnout   (residual 2, final)
    gemm_kernel<true, true, true, true><<<dim3(DMODEL / 64, NTOK / 64, 1), 256>>>(
        ff1, W2, b2, attnout, out,
        FFDIM, FFDIM, FFDIM, DMODEL,
        0, 0, 0, 0, 0, 0);
}

// round 2
// speedup vs baseline: 2.4007x; 2.4007x over previous
#include <cuda_runtime.h>
#include <math.h>
#include <stdint.h>

// ---------------- problem constants ----------------
#define BATCH 8
#define SEQ   1024
#define DMODEL 1024
#define NHEAD 16
#define HDIM  64
#define FFDIM 4096
#define NTOK  (BATCH * SEQ)          // 8192

// ---------------- scratch (device globals, no allocation) ----------------
__device__ float g_h      [(long)NTOK * DMODEL];
__device__ float g_qkv    [(long)NTOK * 3 * DMODEL];
__device__ float g_scores [(long)BATCH * NHEAD * SEQ * SEQ];
__device__ float g_ctx    [(long)NTOK * DMODEL];
__device__ float g_attnout[(long)NTOK * DMODEL];
__device__ float g_h2     [(long)NTOK * DMODEL];
__device__ float g_ff1    [(long)NTOK * FFDIM];

// ---------------- helpers ----------------
__device__ __forceinline__ uint32_t f2tf32(float x) {
    uint32_t u;
    asm("cvt.rna.tf32.f32 %0, %1;" : "=r"(u) : "f"(x));
    return u;
}

__device__ __forceinline__ void mma_tf32(float c[4],
                                         const uint32_t a[4],
                                         const uint32_t b[2]) {
    asm volatile(
        "mma.sync.aligned.m16n8k8.row.col.f32.tf32.tf32.f32 "
        "{%0,%1,%2,%3}, {%4,%5,%6,%7}, {%8,%9}, {%0,%1,%2,%3};\n"
        : "+f"(c[0]), "+f"(c[1]), "+f"(c[2]), "+f"(c[3])
        : "r"(a[0]), "r"(a[1]), "r"(a[2]), "r"(a[3]), "r"(b[0]), "r"(b[1]));
}

__device__ __forceinline__ float gelu_exact(float v) {
    return 0.5f * v * (1.0f + erff(v * 0.70710678118654752f));
}

// ---------------- block reductions (256 threads) ----------------
__device__ __forceinline__ float blockReduceSum(float v, float* sbuf) {
    #pragma unroll
    for (int o = 16; o > 0; o >>= 1) v += __shfl_xor_sync(0xffffffffu, v, o);
    const int w = threadIdx.x >> 5;
    if ((threadIdx.x & 31) == 0) sbuf[w] = v;
    __syncthreads();
    if (threadIdx.x < 32) {
        float t = (threadIdx.x < 8) ? sbuf[threadIdx.x] : 0.0f;
        #pragma unroll
        for (int o = 4; o > 0; o >>= 1) t += __shfl_xor_sync(0xffffffffu, t, o);
        if (threadIdx.x == 0) sbuf[0] = t;
    }
    __syncthreads();
    float r = sbuf[0];
    __syncthreads();
    return r;
}

__device__ __forceinline__ float blockReduceMax(float v, float* sbuf) {
    #pragma unroll
    for (int o = 16; o > 0; o >>= 1) v = fmaxf(v, __shfl_xor_sync(0xffffffffu, v, o));
    const int w = threadIdx.x >> 5;
    if ((threadIdx.x & 31) == 0) sbuf[w] = v;
    __syncthreads();
    if (threadIdx.x < 32) {
        float t = (threadIdx.x < 8) ? sbuf[threadIdx.x] : -3.4e38f;
        #pragma unroll
        for (int o = 4; o > 0; o >>= 1) t = fmaxf(t, __shfl_xor_sync(0xffffffffu, t, o));
        if (threadIdx.x == 0) sbuf[0] = t;
    }
    __syncthreads();
    float r = sbuf[0];
    __syncthreads();
    return r;
}

// ---------------- layernorm: one block per token, 256 threads ----------------
__global__ void layernorm_kernel(const float* __restrict__ x, const float* __restrict__ g,
                                 const float* __restrict__ b, float* __restrict__ out) {
    __shared__ float sbuf[8];
    const long row = blockIdx.x;
    const int tid = threadIdx.x;
    const float4 xv = reinterpret_cast<const float4*>(x + row * DMODEL)[tid];
    float s = xv.x + xv.y + xv.z + xv.w;
    s = blockReduceSum(s, sbuf);
    const float mu = s * (1.0f / (float)DMODEL);
    const float dx = xv.x - mu, dy = xv.y - mu, dz = xv.z - mu, dw = xv.w - mu;
    float vs = dx*dx + dy*dy + dz*dz + dw*dw;
    vs = blockReduceSum(vs, sbuf);
    const float inv = rsqrtf(vs * (1.0f / (float)DMODEL) + 1e-5f);
    const float4 gv = reinterpret_cast<const float4*>(g)[tid];
    const float4 bv = reinterpret_cast<const float4*>(b)[tid];
    float4 o;
    o.x = dx * inv * gv.x + bv.x;
    o.y = dy * inv * gv.y + bv.y;
    o.z = dz * inv * gv.z + bv.z;
    o.w = dw * inv * gv.w + bv.w;
    reinterpret_cast<float4*>(out + row * DMODEL)[tid] = o;
}

// ---------------- softmax over last dim (1024), scale 1/sqrt(HD) ----------------
__global__ void softmax_kernel(float* __restrict__ s) {
    __shared__ float sbuf[8];
    const long row = blockIdx.x;
    float4* p = reinterpret_cast<float4*>(s) + row * (SEQ / 4) + threadIdx.x;
    float4 v = *p;
    const float sc = 0.125f;
    v.x *= sc; v.y *= sc; v.z *= sc; v.w *= sc;
    float m = fmaxf(fmaxf(v.x, v.y), fmaxf(v.z, v.w));
    m = blockReduceMax(m, sbuf);
    v.x = __expf(v.x - m); v.y = __expf(v.y - m);
    v.z = __expf(v.z - m); v.w = __expf(v.w - m);
    float ss = v.x + v.y + v.z + v.w;
    ss = blockReduceSum(ss, sbuf);
    const float inv = 1.0f / ss;
    v.x *= inv; v.y *= inv; v.z *= inv; v.w *= inv;
    *p = v;
}

// ---------------- tf32 tensor-core GEMM ----------------
// out[m,n] = sum_k A[m,k] * (BT ? B[n,k] : B[k,n])  (+bias)(gelu)(+res)
// per-z offsets: off(z) = (z>>4)*s1 + (z&15)*s2
// BM=128, BK=16, 8 warps (2 M x 4 N), warp tile (BM/2) x (BN/4), mma m16n8k8.
template<int BN, bool BT, bool HAS_BIAS, bool GELU, bool HAS_RES>
__global__ void __launch_bounds__(256, 2)
gemm_tc(const float* __restrict__ A, const float* __restrict__ B,
        const float* __restrict__ bias, const float* __restrict__ res,
        float* __restrict__ out,
        int K, int lda, int ldb, int ldo,
        long sA1, long sA2, long sB1, long sB2, long sO1, long sO2)
{
    constexpr int BM = 128;
    constexpr int BK = 16;
    constexpr int WTM = BM / 2;         // 64
    constexpr int WTN = BN / 4;         // 32 or 16
    constexpr int MI = WTM / 16;        // 4
    constexpr int NI = WTN / 8;         // 4 or 2
    constexpr int LDA = BM + 8;         // conflict-free frag loads
    constexpr int LDB = BN + 8;
    constexpr int PA = (BM * BK) / (4 * 256);   // float4 loads per thread for A
    constexpr int PB = (BN * BK) / (4 * 256);   // ... for B

    __shared__ uint32_t As[BK * LDA];
    __shared__ uint32_t Bs[BK * LDB];

    const int z = blockIdx.z;
    A   += (long)(z >> 4) * sA1 + (long)(z & 15) * sA2;
    B   += (long)(z >> 4) * sB1 + (long)(z & 15) * sB2;
    out += (long)(z >> 4) * sO1 + (long)(z & 15) * sO2;
    if (HAS_RES) res += (long)(z >> 4) * sO1 + (long)(z & 15) * sO2;

    const int tid = threadIdx.x;
    const int lane = tid & 31;
    const int warp = tid >> 5;
    const int wm = warp & 1;            // 2 warps in M
    const int wn = warp >> 1;           // 4 warps in N
    const int g = lane >> 2;            // group id (0..7)
    const int t = lane & 3;             // thread-in-group (0..3)
    const int m0 = wm * WTM;
    const int n0 = wn * WTN;
    const int row0 = blockIdx.y * BM;
    const int col0 = blockIdx.x * BN;

    float acc[MI][NI][4];
    #pragma unroll
    for (int mi = 0; mi < MI; mi++)
        #pragma unroll
        for (int ni = 0; ni < NI; ni++)
            #pragma unroll
            for (int q = 0; q < 4; q++) acc[mi][ni][q] = 0.0f;

    float4 areg[PA], breg[PB];

    // ---- prefetch k0 = 0 ----
    #pragma unroll
    for (int p = 0; p < PA; p++) {
        const int idx = p * 256 + tid;
        const int r = idx >> 2, kc = (idx & 3) * 4;
        areg[p] = *reinterpret_cast<const float4*>(A + (long)(row0 + r) * lda + kc);
    }
    #pragma unroll
    for (int p = 0; p < PB; p++) {
        const int idx = p * 256 + tid;
        if (BT) {
            const int r = idx >> 2, kc = (idx & 3) * 4;
            breg[p] = *reinterpret_cast<const float4*>(B + (long)(col0 + r) * ldb + kc);
        } else {
            const int r = idx / (BN / 4), c = (idx % (BN / 4)) * 4;
            breg[p] = *reinterpret_cast<const float4*>(B + (long)r * ldb + col0 + c);
        }
    }

    for (int k0 = 0; k0 < K; k0 += BK) {
        __syncthreads();
        // ---- store staged tile to smem (with tf32 rounding) ----
        #pragma unroll
        for (int p = 0; p < PA; p++) {
            const int idx = p * 256 + tid;
            const int r = idx >> 2, kc = (idx & 3) * 4;
            As[(kc + 0) * LDA + r] = f2tf32(areg[p].x);
            As[(kc + 1) * LDA + r] = f2tf32(areg[p].y);
            As[(kc + 2) * LDA + r] = f2tf32(areg[p].z);
            As[(kc + 3) * LDA + r] = f2tf32(areg[p].w);
        }
        #pragma unroll
        for (int p = 0; p < PB; p++) {
            const int idx = p * 256 + tid;
            if (BT) {
                const int r = idx >> 2, kc = (idx & 3) * 4;
                Bs[(kc + 0) * LDB + r] = f2tf32(breg[p].x);
                Bs[(kc + 1) * LDB + r] = f2tf32(breg[p].y);
                Bs[(kc + 2) * LDB + r] = f2tf32(breg[p].z);
                Bs[(kc + 3) * LDB + r] = f2tf32(breg[p].w);
            } else {
                const int r = idx / (BN / 4), c = (idx % (BN / 4)) * 4;
                uint4 u;
                u.x = f2tf32(breg[p].x); u.y = f2tf32(breg[p].y);
                u.z = f2tf32(breg[p].z); u.w = f2tf32(breg[p].w);
                *reinterpret_cast<uint4*>(&Bs[r * LDB + c]) = u;
            }
        }
        __syncthreads();

        // ---- prefetch next tile while computing this one ----
        if (k0 + BK < K) {
            #pragma unroll
            for (int p = 0; p < PA; p++) {
                const int idx = p * 256 + tid;
                const int r = idx >> 2, kc = (idx & 3) * 4;
                areg[p] = *reinterpret_cast<const float4*>(A + (long)(row0 + r) * lda + k0 + BK + kc);
            }
            #pragma unroll
            for (int p = 0; p < PB; p++) {
                const int idx = p * 256 + tid;
                if (BT) {
                    const int r = idx >> 2, kc = (idx & 3) * 4;
                    breg[p] = *reinterpret_cast<const float4*>(B + (long)(col0 + r) * ldb + k0 + BK + kc);
                } else {
                    const int r = idx / (BN / 4), c = (idx % (BN / 4)) * 4;
                    breg[p] = *reinterpret_cast<const float4*>(B + (long)(k0 + BK + r) * ldb + col0 + c);
                }
            }
        }

        // ---- compute: two k8 steps ----
        #pragma unroll
        for (int kk = 0; kk < BK; kk += 8) {
            uint32_t af[MI][4], bf[NI][2];
            #pragma unroll
            for (int mi = 0; mi < MI; mi++) {
                const int mb = m0 + mi * 16 + g;
                af[mi][0] = As[(kk + t)     * LDA + mb];
                af[mi][1] = As[(kk + t)     * LDA + mb + 8];
                af[mi][2] = As[(kk + t + 4) * LDA + mb];
                af[mi][3] = As[(kk + t + 4) * LDA + mb + 8];
            }
            #pragma unroll
            for (int ni = 0; ni < NI; ni++) {
                const int nb = n0 + ni * 8 + g;
                bf[ni][0] = Bs[(kk + t)     * LDB + nb];
                bf[ni][1] = Bs[(kk + t + 4) * LDB + nb];
            }
            #pragma unroll
            for (int mi = 0; mi < MI; mi++)
                #pragma unroll
                for (int ni = 0; ni < NI; ni++)
                    mma_tf32(acc[mi][ni], af[mi], bf[ni]);
        }
    }

    // ---- epilogue ----
    #pragma unroll
    for (int mi = 0; mi < MI; mi++) {
        #pragma unroll
        for (int ni = 0; ni < NI; ni++) {
            const int c = col0 + n0 + ni * 8 + 2 * t;
            #pragma unroll
            for (int half = 0; half < 2; half++) {
                const int r = row0 + m0 + mi * 16 + g + half * 8;
                float v0 = acc[mi][ni][half * 2 + 0];
                float v1 = acc[mi][ni][half * 2 + 1];
                if (HAS_BIAS) { v0 += bias[c]; v1 += bias[c + 1]; }
                if (GELU)     { v0 = gelu_exact(v0); v1 = gelu_exact(v1); }
                if (HAS_RES) {
                    const float2 rv = *reinterpret_cast<const float2*>(res + (long)r * ldo + c);
                    v0 += rv.x; v1 += rv.y;
                }
                float2 o; o.x = v0; o.y = v1;
                *reinterpret_cast<float2*>(out + (long)r * ldo + c) = o;
            }
        }
    }
}

// ---------------- host launcher ----------------
extern "C" void kernel_launch(void* const* d_in, const int* in_sizes, int n_in,
                              void* d_out, int out_size) {
    const float* x      = (const float*)d_in[0];
    const float* ln1_g  = (const float*)d_in[1];
    const float* ln1_b  = (const float*)d_in[2];
    const float* ln2_g  = (const float*)d_in[3];
    const float* ln2_b  = (const float*)d_in[4];
    const float* W_qkv  = (const float*)d_in[5];
    const float* b_qkv  = (const float*)d_in[6];
    const float* W_proj = (const float*)d_in[7];
    const float* b_proj = (const float*)d_in[8];
    const float* W1     = (const float*)d_in[9];
    const float* b1     = (const float*)d_in[10];
    const float* W2     = (const float*)d_in[11];
    const float* b2     = (const float*)d_in[12];
    float* out = (float*)d_out;

    float *h, *qkv, *scores, *ctx, *attnout, *h2, *ff1;
    cudaGetSymbolAddress((void**)&h,       g_h);
    cudaGetSymbolAddress((void**)&qkv,     g_qkv);
    cudaGetSymbolAddress((void**)&scores,  g_scores);
    cudaGetSymbolAddress((void**)&ctx,     g_ctx);
    cudaGetSymbolAddress((void**)&attnout, g_attnout);
    cudaGetSymbolAddress((void**)&h2,      g_h2);
    cudaGetSymbolAddress((void**)&ff1,     g_ff1);

    const long QKV_B = (long)SEQ * 3 * DMODEL;
    const long SC_Z  = (long)SEQ * SEQ;
    const long CTX_B = (long)SEQ * DMODEL;

    // 1. LN1
    layernorm_kernel<<<NTOK, 256>>>(x, ln1_g, ln1_b, h);

    // 2. qkv = h @ W_qkv^T + b_qkv  [8192 x 3072]
    gemm_tc<128, true, true, false, false><<<dim3(3 * DMODEL / 128, NTOK / 128, 1), 256>>>(
        h, W_qkv, b_qkv, nullptr, qkv,
        DMODEL, DMODEL, DMODEL, 3 * DMODEL,
        0, 0, 0, 0, 0, 0);

    // 3. scores = Q @ K^T  (128 (b,h) batches), K=64
    gemm_tc<128, true, false, false, false><<<dim3(SEQ / 128, SEQ / 128, BATCH * NHEAD), 256>>>(
        qkv, qkv + DMODEL, nullptr, nullptr, scores,
        HDIM, 3 * DMODEL, 3 * DMODEL, SEQ,
        QKV_B, HDIM,
        QKV_B, HDIM,
        16 * SC_Z, SC_Z);

    // 4. softmax
    softmax_kernel<<<BATCH * NHEAD * SEQ, 256>>>(scores);

    // 5. ctx = attn @ V  (batched), B as B[k,n], N=64
    gemm_tc<64, false, false, false, false><<<dim3(1, SEQ / 128, BATCH * NHEAD), 256>>>(
        scores, qkv + 2 * DMODEL, nullptr, nullptr, ctx,
        SEQ, SEQ, 3 * DMODEL, DMODEL,
        16 * SC_Z, SC_Z,
        QKV_B, HDIM,
        CTX_B, HDIM);

    // 6. attnout = ctx @ W_proj^T + b_proj + x
    gemm_tc<128, true, true, false, true><<<dim3(DMODEL / 128, NTOK / 128, 1), 256>>>(
        ctx, W_proj, b_proj, x, attnout,
        DMODEL, DMODEL, DMODEL, DMODEL,
        0, 0, 0, 0, 0, 0);

    // 7. LN2
    layernorm_kernel<<<NTOK, 256>>>(attnout, ln2_g, ln2_b, h2);

    // 8. ff1 = gelu(h2 @ W1^T + b1)  [8192 x 4096]
    gemm_tc<128, true, true, true, false><<<dim3(FFDIM / 128, NTOK / 128, 1), 256>>>(
        h2, W1, b1, nullptr, ff1,
        DMODEL, DMODEL, DMODEL, FFDIM,
        0, 0, 0, 0, 0, 0);

    // 9. out = gelu(ff1 @ W2^T + b2) + attnout
    gemm_tc<128, true, true, true, true><<<dim3(DMODEL / 128, NTOK / 128, 1), 256>>>(
        ff1, W2, b2, attnout, out,
        FFDIM, FFDIM, FFDIM, DMODEL,
        0, 0, 0, 0, 0, 0);
}

// round 3
// speedup vs baseline: 3.7718x; 1.5711x over previous
#include <cuda_runtime.h>
#include <cuda_bf16.h>
#include <math.h>
#include <stdint.h>

// ---------------- problem constants ----------------
#define BATCH 8
#define SEQ   1024
#define DMODEL 1024
#define NHEAD 16
#define HDIM  64
#define FFDIM 4096
#define NTOK  (BATCH * SEQ)          // 8192

// ---------------- scratch (device globals, no allocation) ----------------
__device__ float g_h      [(long)NTOK * DMODEL];
__device__ float g_qkv    [(long)NTOK * 3 * DMODEL];
__device__ float g_scores [(long)BATCH * NHEAD * SEQ * SEQ];
__device__ float g_ctx    [(long)NTOK * DMODEL];
__device__ float g_attnout[(long)NTOK * DMODEL];
__device__ float g_h2     [(long)NTOK * DMODEL];
__device__ float g_ff1    [(long)NTOK * FFDIM];

// ---------------- helpers ----------------
__device__ __forceinline__ uint32_t packbf(float lo, float hi) {
    __nv_bfloat162 v = __float22bfloat162_rn(make_float2(lo, hi));
    return *reinterpret_cast<uint32_t*>(&v);
}

__device__ __forceinline__ void mma_bf16(float c[4],
                                         const uint32_t a[4],
                                         const uint32_t b[2]) {
    asm volatile(
        "mma.sync.aligned.m16n8k16.row.col.f32.bf16.bf16.f32 "
        "{%0,%1,%2,%3}, {%4,%5,%6,%7}, {%8,%9}, {%0,%1,%2,%3};\n"
        : "+f"(c[0]), "+f"(c[1]), "+f"(c[2]), "+f"(c[3])
        : "r"(a[0]), "r"(a[1]), "r"(a[2]), "r"(a[3]), "r"(b[0]), "r"(b[1]));
}

__device__ __forceinline__ float gelu_exact(float v) {
    return 0.5f * v * (1.0f + erff(v * 0.70710678118654752f));
}

// ---------------- block reductions (256 threads) ----------------
__device__ __forceinline__ float blockReduceSum(float v, float* sbuf) {
    #pragma unroll
    for (int o = 16; o > 0; o >>= 1) v += __shfl_xor_sync(0xffffffffu, v, o);
    const int w = threadIdx.x >> 5;
    if ((threadIdx.x & 31) == 0) sbuf[w] = v;
    __syncthreads();
    if (threadIdx.x < 32) {
        float t = (threadIdx.x < 8) ? sbuf[threadIdx.x] : 0.0f;
        #pragma unroll
        for (int o = 4; o > 0; o >>= 1) t += __shfl_xor_sync(0xffffffffu, t, o);
        if (threadIdx.x == 0) sbuf[0] = t;
    }
    __syncthreads();
    float r = sbuf[0];
    __syncthreads();
    return r;
}

__device__ __forceinline__ float blockReduceMax(float v, float* sbuf) {
    #pragma unroll
    for (int o = 16; o > 0; o >>= 1) v = fmaxf(v, __shfl_xor_sync(0xffffffffu, v, o));
    const int w = threadIdx.x >> 5;
    if ((threadIdx.x & 31) == 0) sbuf[w] = v;
    __syncthreads();
    if (threadIdx.x < 32) {
        float t = (threadIdx.x < 8) ? sbuf[threadIdx.x] : -3.4e38f;
        #pragma unroll
        for (int o = 4; o > 0; o >>= 1) t = fmaxf(t, __shfl_xor_sync(0xffffffffu, t, o));
        if (threadIdx.x == 0) sbuf[0] = t;
    }
    __syncthreads();
    float r = sbuf[0];
    __syncthreads();
    return r;
}

// ---------------- layernorm: one block per token, 256 threads ----------------
__global__ void layernorm_kernel(const float* __restrict__ x, const float* __restrict__ g,
                                 const float* __restrict__ b, float* __restrict__ out) {
    __shared__ float sbuf[8];
    const long row = blockIdx.x;
    const int tid = threadIdx.x;
    const float4 xv = reinterpret_cast<const float4*>(x + row * DMODEL)[tid];
    float s = xv.x + xv.y + xv.z + xv.w;
    s = blockReduceSum(s, sbuf);
    const float mu = s * (1.0f / (float)DMODEL);
    const float dx = xv.x - mu, dy = xv.y - mu, dz = xv.z - mu, dw = xv.w - mu;
    float vs = dx*dx + dy*dy + dz*dz + dw*dw;
    vs = blockReduceSum(vs, sbuf);
    const float inv = rsqrtf(vs * (1.0f / (float)DMODEL) + 1e-5f);
    const float4 gv = reinterpret_cast<const float4*>(g)[tid];
    const float4 bv = reinterpret_cast<const float4*>(b)[tid];
    float4 o;
    o.x = dx * inv * gv.x + bv.x;
    o.y = dy * inv * gv.y + bv.y;
    o.z = dz * inv * gv.z + bv.z;
    o.w = dw * inv * gv.w + bv.w;
    reinterpret_cast<float4*>(out + row * DMODEL)[tid] = o;
}

// ---------------- softmax over last dim (1024), scale 1/sqrt(HD) ----------------
__global__ void softmax_kernel(float* __restrict__ s) {
    __shared__ float sbuf[8];
    const long row = blockIdx.x;
    float4* p = reinterpret_cast<float4*>(s) + row * (SEQ / 4) + threadIdx.x;
    float4 v = *p;
    const float sc = 0.125f;
    v.x *= sc; v.y *= sc; v.z *= sc; v.w *= sc;
    float m = fmaxf(fmaxf(v.x, v.y), fmaxf(v.z, v.w));
    m = blockReduceMax(m, sbuf);
    v.x = __expf(v.x - m); v.y = __expf(v.y - m);
    v.z = __expf(v.z - m); v.w = __expf(v.w - m);
    float ss = v.x + v.y + v.z + v.w;
    ss = blockReduceSum(ss, sbuf);
    const float inv = 1.0f / ss;
    v.x *= inv; v.y *= inv; v.z *= inv; v.w *= inv;
    *p = v;
}

// ---------------- bf16 tensor-core GEMM, double buffered ----------------
// out[m,n] = sum_k A[m,k] * (BT ? B[n,k] : B[k,n])  (+bias)(gelu)(+res)
// fp32 in gmem; converted to bf16 while staging to smem.
// BM=128, BK=32, 8 warps (2 M x 4 N), warp tile 64 x (BN/4), mma m16n8k16.
// smem layout: m/n-major, LDK=20 uint32 (16 k-pairs + 4 pad) -> conflict-free
// fragment loads (bank = (20g + t) mod 32 is a perfect partition).
template<int BN, bool BT, bool HAS_BIAS, bool GELU, bool HAS_RES>
__global__ void __launch_bounds__(256)
gemm_bf16(const float* __restrict__ A, const float* __restrict__ B,
          const float* __restrict__ bias, const float* __restrict__ res,
          float* __restrict__ out,
          int K, int lda, int ldb, int ldo,
          long sA1, long sA2, long sB1, long sB2, long sO1, long sO2)
{
    constexpr int BM = 128;
    constexpr int BK = 32;
    constexpr int WTN = BN / 4;          // 32 or 16
    constexpr int MI = 4;                // 64 / 16
    constexpr int NI = WTN / 8;          // 4 or 2
    constexpr int LDK = 20;              // uint32 per m/n row (16 pairs + 4 pad)
    constexpr int PA = (BM * BK) / (4 * 256);        // 4 float4 per thread
    constexpr int PBT = (BN * BK) / (4 * 256);       // BT: float4 per thread
    static_assert(BT || BN == 64, "non-transposed B path only for BN=64");

    __shared__ uint32_t As[2][BM * LDK];
    __shared__ uint32_t Bs[2][BN * LDK];

    const int z = blockIdx.z;
    A   += (long)(z >> 4) * sA1 + (long)(z & 15) * sA2;
    B   += (long)(z >> 4) * sB1 + (long)(z & 15) * sB2;
    out += (long)(z >> 4) * sO1 + (long)(z & 15) * sO2;
    if (HAS_RES) res += (long)(z >> 4) * sO1 + (long)(z & 15) * sO2;

    const int tid = threadIdx.x;
    const int lane = tid & 31;
    const int warp = tid >> 5;
    const int wm = warp & 1;
    const int wn = warp >> 1;
    const int g = lane >> 2;
    const int t = lane & 3;
    const int m0 = wm * 64;
    const int n0 = wn * WTN;
    const int row0 = blockIdx.y * BM;
    const int col0 = blockIdx.x * BN;

    float acc[MI][NI][4];
    #pragma unroll
    for (int mi = 0; mi < MI; mi++)
        #pragma unroll
        for (int ni = 0; ni < NI; ni++)
            #pragma unroll
            for (int q = 0; q < 4; q++) acc[mi][ni][q] = 0.0f;

    float4 areg[PA];
    float4 bregT[BT ? PBT : 1];
    float  bregN[BT ? 1 : 8];

    // ---- staging lambdas ----
    auto load_tiles = [&](int k0) {
        #pragma unroll
        for (int p = 0; p < PA; p++) {
            const int idx = p * 256 + tid;
            const int r = idx >> 3, kc = (idx & 7) << 2;
            areg[p] = *reinterpret_cast<const float4*>(A + (long)(row0 + r) * lda + k0 + kc);
        }
        if constexpr (BT) {
            #pragma unroll
            for (int p = 0; p < PBT; p++) {
                const int idx = p * 256 + tid;
                const int r = idx >> 3, kc = (idx & 7) << 2;
                bregT[p] = *reinterpret_cast<const float4*>(B + (long)(col0 + r) * ldb + k0 + kc);
            }
        } else {
            const int n = tid & 63;
            const int kb = (tid >> 6) * 8;   // 8 consecutive k rows
            #pragma unroll
            for (int j = 0; j < 8; j++)
                bregN[j] = B[(long)(k0 + kb + j) * ldb + col0 + n];
        }
    };

    auto store_tiles = [&](int buf) {
        #pragma unroll
        for (int p = 0; p < PA; p++) {
            const int idx = p * 256 + tid;
            const int r = idx >> 3, kc = (idx & 7) << 2;
            uint2 u;
            u.x = packbf(areg[p].x, areg[p].y);
            u.y = packbf(areg[p].z, areg[p].w);
            *reinterpret_cast<uint2*>(&As[buf][r * LDK + (kc >> 1)]) = u;
        }
        if constexpr (BT) {
            #pragma unroll
            for (int p = 0; p < PBT; p++) {
                const int idx = p * 256 + tid;
                const int r = idx >> 3, kc = (idx & 7) << 2;
                uint2 u;
                u.x = packbf(bregT[p].x, bregT[p].y);
                u.y = packbf(bregT[p].z, bregT[p].w);
                *reinterpret_cast<uint2*>(&Bs[buf][r * LDK + (kc >> 1)]) = u;
            }
        } else {
            const int n = tid & 63;
            const int kp4 = tid >> 6;        // 4 consecutive k-pairs
            uint4 u;
            u.x = packbf(bregN[0], bregN[1]);
            u.y = packbf(bregN[2], bregN[3]);
            u.z = packbf(bregN[4], bregN[5]);
            u.w = packbf(bregN[6], bregN[7]);
            *reinterpret_cast<uint4*>(&Bs[buf][n * LDK + kp4 * 4]) = u;
        }
    };

    auto compute = [&](int buf) {
        #pragma unroll
        for (int kk2 = 0; kk2 < 16; kk2 += 8) {   // two k16 steps
            uint32_t af[MI][4], bf[NI][2];
            #pragma unroll
            for (int mi = 0; mi < MI; mi++) {
                const int mb = m0 + mi * 16 + g;
                af[mi][0] = As[buf][(mb)     * LDK + kk2 + t];
                af[mi][1] = As[buf][(mb + 8) * LDK + kk2 + t];
                af[mi][2] = As[buf][(mb)     * LDK + kk2 + t + 4];
                af[mi][3] = As[buf][(mb + 8) * LDK + kk2 + t + 4];
            }
            #pragma unroll
            for (int ni = 0; ni < NI; ni++) {
                const int nb = n0 + ni * 8 + g;
                bf[ni][0] = Bs[buf][nb * LDK + kk2 + t];
                bf[ni][1] = Bs[buf][nb * LDK + kk2 + t + 4];
            }
            #pragma unroll
            for (int mi = 0; mi < MI; mi++)
                #pragma unroll
                for (int ni = 0; ni < NI; ni++)
                    mma_bf16(acc[mi][ni], af[mi], bf[ni]);
        }
    };

    // ---- main loop, double buffered, one sync per tile ----
    const int nt = K / BK;
    load_tiles(0);
    store_tiles(0);
    __syncthreads();
    for (int it = 0; it < nt; it++) {
        const int cur = it & 1;
        const bool more = (it + 1 < nt);
        if (more) load_tiles((it + 1) * BK);
        compute(cur);
        if (more) store_tiles(cur ^ 1);
        __syncthreads();
    }

    // ---- epilogue ----
    #pragma unroll
    for (int mi = 0; mi < MI; mi++) {
        #pragma unroll
        for (int ni = 0; ni < NI; ni++) {
            const int c = col0 + n0 + ni * 8 + 2 * t;
            #pragma unroll
            for (int half = 0; half < 2; half++) {
                const int r = row0 + m0 + mi * 16 + g + half * 8;
                float v0 = acc[mi][ni][half * 2 + 0];
                float v1 = acc[mi][ni][half * 2 + 1];
                if (HAS_BIAS) { v0 += bias[c]; v1 += bias[c + 1]; }
                if (GELU)     { v0 = gelu_exact(v0); v1 = gelu_exact(v1); }
                if (HAS_RES) {
                    const float2 rv = *reinterpret_cast<const float2*>(res + (long)r * ldo + c);
                    v0 += rv.x; v1 += rv.y;
                }
                float2 o; o.x = v0; o.y = v1;
                *reinterpret_cast<float2*>(out + (long)r * ldo + c) = o;
            }
        }
    }
}

// ---------------- host launcher ----------------
extern "C" void kernel_launch(void* const* d_in, const int* in_sizes, int n_in,
                              void* d_out, int out_size) {
    const float* x      = (const float*)d_in[0];
    const float* ln1_g  = (const float*)d_in[1];
    const float* ln1_b  = (const float*)d_in[2];
    const float* ln2_g  = (const float*)d_in[3];
    const float* ln2_b  = (const float*)d_in[4];
    const float* W_qkv  = (const float*)d_in[5];
    const float* b_qkv  = (const float*)d_in[6];
    const float* W_proj = (const float*)d_in[7];
    const float* b_proj = (const float*)d_in[8];
    const float* W1     = (const float*)d_in[9];
    const float* b1     = (const float*)d_in[10];
    const float* W2     = (const float*)d_in[11];
    const float* b2     = (const float*)d_in[12];
    float* out = (float*)d_out;

    float *h, *qkv, *scores, *ctx, *attnout, *h2, *ff1;
    cudaGetSymbolAddress((void**)&h,       g_h);
    cudaGetSymbolAddress((void**)&qkv,     g_qkv);
    cudaGetSymbolAddress((void**)&scores,  g_scores);
    cudaGetSymbolAddress((void**)&ctx,     g_ctx);
    cudaGetSymbolAddress((void**)&attnout, g_attnout);
    cudaGetSymbolAddress((void**)&h2,      g_h2);
    cudaGetSymbolAddress((void**)&ff1,     g_ff1);

    const long QKV_B = (long)SEQ * 3 * DMODEL;
    const long SC_Z  = (long)SEQ * SEQ;
    const long CTX_B = (long)SEQ * DMODEL;

    // 1. LN1
    layernorm_kernel<<<NTOK, 256>>>(x, ln1_g, ln1_b, h);

    // 2. qkv = h @ W_qkv^T + b_qkv  [8192 x 3072]
    gemm_bf16<128, true, true, false, false><<<dim3(3 * DMODEL / 128, NTOK / 128, 1), 256>>>(
        h, W_qkv, b_qkv, nullptr, qkv,
        DMODEL, DMODEL, DMODEL, 3 * DMODEL,
        0, 0, 0, 0, 0, 0);

    // 3. scores = Q @ K^T  (128 (b,h) batches), K=64
    gemm_bf16<128, true, false, false, false><<<dim3(SEQ / 128, SEQ / 128, BATCH * NHEAD), 256>>>(
        qkv, qkv + DMODEL, nullptr, nullptr, scores,
        HDIM, 3 * DMODEL, 3 * DMODEL, SEQ,
        QKV_B, HDIM,
        QKV_B, HDIM,
        16 * SC_Z, SC_Z);

    // 4. softmax
    softmax_kernel<<<BATCH * NHEAD * SEQ, 256>>>(scores);

    // 5. ctx = attn @ V  (batched), B as B[k,n], N=64
    gemm_bf16<64, false, false, false, false><<<dim3(1, SEQ / 128, BATCH * NHEAD), 256>>>(
        scores, qkv + 2 * DMODEL, nullptr, nullptr, ctx,
        SEQ, SEQ, 3 * DMODEL, DMODEL,
        16 * SC_Z, SC_Z,
        QKV_B, HDIM,
        CTX_B, HDIM);

    // 6. attnout = ctx @ W_proj^T + b_proj + x
    gemm_bf16<128, true, true, false, true><<<dim3(DMODEL / 128, NTOK / 128, 1), 256>>>(
        ctx, W_proj, b_proj, x, attnout,
        DMODEL, DMODEL, DMODEL, DMODEL,
        0, 0, 0, 0, 0, 0);

    // 7. LN2
    layernorm_kernel<<<NTOK, 256>>>(attnout, ln2_g, ln2_b, h2);

    // 8. ff1 = gelu(h2 @ W1^T + b1)  [8192 x 4096]
    gemm_bf16<128, true, true, true, false><<<dim3(FFDIM / 128, NTOK / 128, 1), 256>>>(
        h2, W1, b1, nullptr, ff1,
        DMODEL, DMODEL, DMODEL, FFDIM,
        0, 0, 0, 0, 0, 0);

    // 9. out = gelu(ff1 @ W2^T + b2) + attnout
    gemm_bf16<128, true, true, true, true><<<dim3(DMODEL / 128, NTOK / 128, 1), 256>>>(
        ff1, W2, b2, attnout, out,
        FFDIM, FFDIM, FFDIM, DMODEL,
        0, 0, 0, 0, 0, 0);
}

// round 4
// speedup vs baseline: 3.7773x; 1.0015x over previous
#include <cuda_runtime.h>
#include <cuda_bf16.h>
#include <math.h>
#include <stdint.h>

// ---------------- problem constants ----------------
#define BATCH 8
#define SEQ   1024
#define DMODEL 1024
#define NHEAD 16
#define HDIM  64
#define FFDIM 4096
#define NTOK  (BATCH * SEQ)          // 8192

// ---------------- scratch (device globals, no allocation) ----------------
__device__ float g_h      [(long)NTOK * DMODEL];
__device__ float g_qkv    [(long)NTOK * 3 * DMODEL];
__device__ float g_scores [(long)BATCH * NHEAD * SEQ * SEQ];
__device__ float g_ctx    [(long)NTOK * DMODEL];
__device__ float g_attnout[(long)NTOK * DMODEL];
__device__ float g_h2     [(long)NTOK * DMODEL];
__device__ float g_ff1    [(long)NTOK * FFDIM];

// ---------------- helpers ----------------
__device__ __forceinline__ uint32_t packbf(float lo, float hi) {
    __nv_bfloat162 v = __float22bfloat162_rn(make_float2(lo, hi));
    return *reinterpret_cast<uint32_t*>(&v);
}

__device__ __forceinline__ void mma_bf16(float c[4],
                                         const uint32_t a[4],
                                         const uint32_t b[2]) {
    asm volatile(
        "mma.sync.aligned.m16n8k16.row.col.f32.bf16.bf16.f32 "
        "{%0,%1,%2,%3}, {%4,%5,%6,%7}, {%8,%9}, {%0,%1,%2,%3};\n"
        : "+f"(c[0]), "+f"(c[1]), "+f"(c[2]), "+f"(c[3])
        : "r"(a[0]), "r"(a[1]), "r"(a[2]), "r"(a[3]), "r"(b[0]), "r"(b[1]));
}

__device__ __forceinline__ float gelu_exact(float v) {
    return 0.5f * v * (1.0f + erff(v * 0.70710678118654752f));
}

// ---------------- block reductions (256 threads) ----------------
__device__ __forceinline__ float blockReduceSum(float v, float* sbuf) {
    #pragma unroll
    for (int o = 16; o > 0; o >>= 1) v += __shfl_xor_sync(0xffffffffu, v, o);
    const int w = threadIdx.x >> 5;
    if ((threadIdx.x & 31) == 0) sbuf[w] = v;
    __syncthreads();
    if (threadIdx.x < 32) {
        float t = (threadIdx.x < 8) ? sbuf[threadIdx.x] : 0.0f;
        #pragma unroll
        for (int o = 4; o > 0; o >>= 1) t += __shfl_xor_sync(0xffffffffu, t, o);
        if (threadIdx.x == 0) sbuf[0] = t;
    }
    __syncthreads();
    float r = sbuf[0];
    __syncthreads();
    return r;
}

__device__ __forceinline__ float blockReduceMax(float v, float* sbuf) {
    #pragma unroll
    for (int o = 16; o > 0; o >>= 1) v = fmaxf(v, __shfl_xor_sync(0xffffffffu, v, o));
    const int w = threadIdx.x >> 5;
    if ((threadIdx.x & 31) == 0) sbuf[w] = v;
    __syncthreads();
    if (threadIdx.x < 32) {
        float t = (threadIdx.x < 8) ? sbuf[threadIdx.x] : -3.4e38f;
        #pragma unroll
        for (int o = 4; o > 0; o >>= 1) t = fmaxf(t, __shfl_xor_sync(0xffffffffu, t, o));
        if (threadIdx.x == 0) sbuf[0] = t;
    }
    __syncthreads();
    float r = sbuf[0];
    __syncthreads();
    return r;
}

// ---------------- layernorm: one block per token, 256 threads ----------------
__global__ void layernorm_kernel(const float* __restrict__ x, const float* __restrict__ g,
                                 const float* __restrict__ b, float* __restrict__ out) {
    __shared__ float sbuf[8];
    const long row = blockIdx.x;
    const int tid = threadIdx.x;
    const float4 xv = reinterpret_cast<const float4*>(x + row * DMODEL)[tid];
    float s = xv.x + xv.y + xv.z + xv.w;
    s = blockReduceSum(s, sbuf);
    const float mu = s * (1.0f / (float)DMODEL);
    const float dx = xv.x - mu, dy = xv.y - mu, dz = xv.z - mu, dw = xv.w - mu;
    float vs = dx*dx + dy*dy + dz*dz + dw*dw;
    vs = blockReduceSum(vs, sbuf);
    const float inv = rsqrtf(vs * (1.0f / (float)DMODEL) + 1e-5f);
    const float4 gv = reinterpret_cast<const float4*>(g)[tid];
    const float4 bv = reinterpret_cast<const float4*>(b)[tid];
    float4 o;
    o.x = dx * inv * gv.x + bv.x;
    o.y = dy * inv * gv.y + bv.y;
    o.z = dz * inv * gv.z + bv.z;
    o.w = dw * inv * gv.w + bv.w;
    reinterpret_cast<float4*>(out + row * DMODEL)[tid] = o;
}

// ---------------- softmax over last dim (1024), scale 1/sqrt(HD) ----------------
__global__ void softmax_kernel(float* __restrict__ s) {
    __shared__ float sbuf[8];
    const long row = blockIdx.x;
    float4* p = reinterpret_cast<float4*>(s) + row * (SEQ / 4) + threadIdx.x;
    float4 v = *p;
    const float sc = 0.125f;
    v.x *= sc; v.y *= sc; v.z *= sc; v.w *= sc;
    float m = fmaxf(fmaxf(v.x, v.y), fmaxf(v.z, v.w));
    m = blockReduceMax(m, sbuf);
    v.x = __expf(v.x - m); v.y = __expf(v.y - m);
    v.z = __expf(v.z - m); v.w = __expf(v.w - m);
    float ss = v.x + v.y + v.z + v.w;
    ss = blockReduceSum(ss, sbuf);
    const float inv = 1.0f / ss;
    v.x *= inv; v.y *= inv; v.z *= inv; v.w *= inv;
    *p = v;
}

// ---------------- bf16 tensor-core GEMM, double buffered ----------------
// out[m,n] = sum_k A[m,k] * (BT ? B[n,k] : B[k,n])  (+bias)(gelu)(+res)
// fp32 in gmem; converted to bf16 while staging to smem.
// BM=128, BK=32, 8 warps (2 M x 4 N), warp tile 64 x (BN/4), mma m16n8k16.
// smem layout: m/n-major, LDK=20 uint32 (16 k-pairs + 4 pad) -> conflict-free
// fragment loads (bank = (20g + t) mod 32 is a perfect partition).
template<int BN, bool BT, bool HAS_BIAS, bool GELU, bool HAS_RES>
__global__ void __launch_bounds__(256)
gemm_bf16(const float* __restrict__ A, const float* __restrict__ B,
          const float* __restrict__ bias, const float* __restrict__ res,
          float* __restrict__ out,
          int K, int lda, int ldb, int ldo,
          long sA1, long sA2, long sB1, long sB2, long sO1, long sO2)
{
    constexpr int BM = 128;
    constexpr int BK = 32;
    constexpr int WTN = BN / 4;          // 32 or 16
    constexpr int MI = 4;                // 64 / 16
    constexpr int NI = WTN / 8;          // 4 or 2
    constexpr int LDK = 20;              // uint32 per m/n row (16 pairs + 4 pad)
    constexpr int PA = (BM * BK) / (4 * 256);        // 4 float4 per thread
    constexpr int PBT = (BN * BK) / (4 * 256);       // BT: float4 per thread
    static_assert(BT || BN == 64, "non-transposed B path only for BN=64");

    __shared__ uint32_t As[2][BM * LDK];
    __shared__ uint32_t Bs[2][BN * LDK];

    const int z = blockIdx.z;
    A   += (long)(z >> 4) * sA1 + (long)(z & 15) * sA2;
    B   += (long)(z >> 4) * sB1 + (long)(z & 15) * sB2;
    out += (long)(z >> 4) * sO1 + (long)(z & 15) * sO2;
    if (HAS_RES) res += (long)(z >> 4) * sO1 + (long)(z & 15) * sO2;

    const int tid = threadIdx.x;
    const int lane = tid & 31;
    const int warp = tid >> 5;
    const int wm = warp & 1;
    const int wn = warp >> 1;
    const int g = lane >> 2;
    const int t = lane & 3;
    const int m0 = wm * 64;
    const int n0 = wn * WTN;
    const int row0 = blockIdx.y * BM;
    const int col0 = blockIdx.x * BN;

    float acc[MI][NI][4];
    #pragma unroll
    for (int mi = 0; mi < MI; mi++)
        #pragma unroll
        for (int ni = 0; ni < NI; ni++)
            #pragma unroll
            for (int q = 0; q < 4; q++) acc[mi][ni][q] = 0.0f;

    float4 areg[PA];
    float4 bregT[BT ? PBT : 1];
    float  bregN[BT ? 1 : 8];

    // ---- staging lambdas ----
    auto load_tiles = [&](int k0) {
        #pragma unroll
        for (int p = 0; p < PA; p++) {
            const int idx = p * 256 + tid;
            const int r = idx >> 3, kc = (idx & 7) << 2;
            areg[p] = *reinterpret_cast<const float4*>(A + (long)(row0 + r) * lda + k0 + kc);
        }
        if constexpr (BT) {
            #pragma unroll
            for (int p = 0; p < PBT; p++) {
                const int idx = p * 256 + tid;
                const int r = idx >> 3, kc = (idx & 7) << 2;
                bregT[p] = *reinterpret_cast<const float4*>(B + (long)(col0 + r) * ldb + k0 + kc);
            }
        } else {
            const int n = tid & 63;
            const int kb = (tid >> 6) * 8;   // 8 consecutive k rows
            #pragma unroll
            for (int j = 0; j < 8; j++)
                bregN[j] = B[(long)(k0 + kb + j) * ldb + col0 + n];
        }
    };

    auto store_tiles = [&](int buf) {
        #pragma unroll
        for (int p = 0; p < PA; p++) {
            const int idx = p * 256 + tid;
            const int r = idx >> 3, kc = (idx & 7) << 2;
            uint2 u;
            u.x = packbf(areg[p].x, areg[p].y);
            u.y = packbf(areg[p].z, areg[p].w);
            *reinterpret_cast<uint2*>(&As[buf][r * LDK + (kc >> 1)]) = u;
        }
        if constexpr (BT) {
            #pragma unroll
            for (int p = 0; p < PBT; p++) {
                const int idx = p * 256 + tid;
                const int r = idx >> 3, kc = (idx & 7) << 2;
                uint2 u;
                u.x = packbf(bregT[p].x, bregT[p].y);
                u.y = packbf(bregT[p].z, bregT[p].w);
                *reinterpret_cast<uint2*>(&Bs[buf][r * LDK + (kc >> 1)]) = u;
            }
        } else {
            const int n = tid & 63;
            const int kp4 = tid >> 6;        // 4 consecutive k-pairs
            uint4 u;
            u.x = packbf(bregN[0], bregN[1]);
            u.y = packbf(bregN[2], bregN[3]);
            u.z = packbf(bregN[4], bregN[5]);
            u.w = packbf(bregN[6], bregN[7]);
            *reinterpret_cast<uint4*>(&Bs[buf][n * LDK + kp4 * 4]) = u;
        }
    };

    auto compute = [&](int buf) {
        #pragma unroll
        for (int kk2 = 0; kk2 < 16; kk2 += 8) {   // two k16 steps
            uint32_t af[MI][4], bf[NI][2];
            #pragma unroll
            for (int mi = 0; mi < MI; mi++) {
                const int mb = m0 + mi * 16 + g;
                af[mi][0] = As[buf][(mb)     * LDK + kk2 + t];
                af[mi][1] = As[buf][(mb + 8) * LDK + kk2 + t];
                af[mi][2] = As[buf][(mb)     * LDK + kk2 + t + 4];
                af[mi][3] = As[buf][(mb + 8) * LDK + kk2 + t + 4];
            }
            #pragma unroll
            for (int ni = 0; ni < NI; ni++) {
                const int nb = n0 + ni * 8 + g;
                bf[ni][0] = Bs[buf][nb * LDK + kk2 + t];
                bf[ni][1] = Bs[buf][nb * LDK + kk2 + t + 4];
            }
            #pragma unroll
            for (int mi = 0; mi < MI; mi++)
                #pragma unroll
                for (int ni = 0; ni < NI; ni++)
                    mma_bf16(acc[mi][ni], af[mi], bf[ni]);
        }
    };

    // ---- main loop, double buffered, one sync per tile ----
    const int nt = K / BK;
    load_tiles(0);
    store_tiles(0);
    __syncthreads();
    for (int it = 0; it < nt; it++) {
        const int cur = it & 1;
        const bool more = (it + 1 < nt);
        if (more) load_tiles((it + 1) * BK);
        compute(cur);
        if (more) store_tiles(cur ^ 1);
        __syncthreads();
    }

    // ---- epilogue ----
    #pragma unroll
    for (int mi = 0; mi < MI; mi++) {
        #pragma unroll
        for (int ni = 0; ni < NI; ni++) {
            const int c = col0 + n0 + ni * 8 + 2 * t;
            #pragma unroll
            for (int half = 0; half < 2; half++) {
                const int r = row0 + m0 + mi * 16 + g + half * 8;
                float v0 = acc[mi][ni][half * 2 + 0];
                float v1 = acc[mi][ni][half * 2 + 1];
                if (HAS_BIAS) { v0 += bias[c]; v1 += bias[c + 1]; }
                if (GELU)     { v0 = gelu_exact(v0); v1 = gelu_exact(v1); }
                if (HAS_RES) {
                    const float2 rv = *reinterpret_cast<const float2*>(res + (long)r * ldo + c);
                    v0 += rv.x; v1 += rv.y;
                }
                float2 o; o.x = v0; o.y = v1;
                *reinterpret_cast<float2*>(out + (long)r * ldo + c) = o;
            }
        }
    }
}

// ---------------- host launcher ----------------
extern "C" void kernel_launch(void* const* d_in, const int* in_sizes, int n_in,
                              void* d_out, int out_size) {
    const float* x      = (const float*)d_in[0];
    const float* ln1_g  = (const float*)d_in[1];
    const float* ln1_b  = (const float*)d_in[2];
    const float* ln2_g  = (const float*)d_in[3];
    const float* ln2_b  = (const float*)d_in[4];
    const float* W_qkv  = (const float*)d_in[5];
    const float* b_qkv  = (const float*)d_in[6];
    const float* W_proj = (const float*)d_in[7];
    const float* b_proj = (const float*)d_in[8];
    const float* W1     = (const float*)d_in[9];
    const float* b1     = (const float*)d_in[10];
    const float* W2     = (const float*)d_in[11];
    const float* b2     = (const float*)d_in[12];
    float* out = (float*)d_out;

    float *h, *qkv, *scores, *ctx, *attnout, *h2, *ff1;
    cudaGetSymbolAddress((void**)&h,       g_h);
    cudaGetSymbolAddress((void**)&qkv,     g_qkv);
    cudaGetSymbolAddress((void**)&scores,  g_scores);
    cudaGetSymbolAddress((void**)&ctx,     g_ctx);
    cudaGetSymbolAddress((void**)&attnout, g_attnout);
    cudaGetSymbolAddress((void**)&h2,      g_h2);
    cudaGetSymbolAddress((void**)&ff1,     g_ff1);

    const long QKV_B = (long)SEQ * 3 * DMODEL;
    const long SC_Z  = (long)SEQ * SEQ;
    const long CTX_B = (long)SEQ * DMODEL;

    // 1. LN1
    layernorm_kernel<<<NTOK, 256>>>(x, ln1_g, ln1_b, h);

    // 2. qkv = h @ W_qkv^T + b_qkv  [8192 x 3072]
    gemm_bf16<128, true, true, false, false><<<dim3(3 * DMODEL / 128, NTOK / 128, 1), 256>>>(
        h, W_qkv, b_qkv, nullptr, qkv,
        DMODEL, DMODEL, DMODEL, 3 * DMODEL,
        0, 0, 0, 0, 0, 0);

    // 3. scores = Q @ K^T  (128 (b,h) batches), K=64
    gemm_bf16<128, true, false, false, false><<<dim3(SEQ / 128, SEQ / 128, BATCH * NHEAD), 256>>>(
        qkv, qkv + DMODEL, nullptr, nullptr, scores,
        HDIM, 3 * DMODEL, 3 * DMODEL, SEQ,
        QKV_B, HDIM,
        QKV_B, HDIM,
        16 * SC_Z, SC_Z);

    // 4. softmax
    softmax_kernel<<<BATCH * NHEAD * SEQ, 256>>>(scores);

    // 5. ctx = attn @ V  (batched), B as B[k,n], N=64
    gemm_bf16<64, false, false, false, false><<<dim3(1, SEQ / 128, BATCH * NHEAD), 256>>>(
        scores, qkv + 2 * DMODEL, nullptr, nullptr, ctx,
        SEQ, SEQ, 3 * DMODEL, DMODEL,
        16 * SC_Z, SC_Z,
        QKV_B, HDIM,
        CTX_B, HDIM);

    // 6. attnout = ctx @ W_proj^T + b_proj + x
    gemm_bf16<128, true, true, false, true><<<dim3(DMODEL / 128, NTOK / 128, 1), 256>>>(
        ctx, W_proj, b_proj, x, attnout,
        DMODEL, DMODEL, DMODEL, DMODEL,
        0, 0, 0, 0, 0, 0);

    // 7. LN2
    layernorm_kernel<<<NTOK, 256>>>(attnout, ln2_g, ln2_b, h2);

    // 8. ff1 = gelu(h2 @ W1^T + b1)  [8192 x 4096]
    gemm_bf16<128, true, true, true, false><<<dim3(FFDIM / 128, NTOK / 128, 1), 256>>>(
        h2, W1, b1, nullptr, ff1,
        DMODEL, DMODEL, DMODEL, FFDIM,
        0, 0, 0, 0, 0, 0);

    // 9. out = gelu(ff1 @ W2^T + b2) + attnout
    gemm_bf16<128, true, true, true, true><<<dim3(DMODEL / 128, NTOK / 128, 1), 256>>>(
        ff1, W2, b2, attnout, out,
        FFDIM, FFDIM, FFDIM, DMODEL,
        0, 0, 0, 0, 0, 0);
}

// round 5
// speedup vs baseline: 7.1743x; 1.8993x over previous
#include <cuda_runtime.h>
#include <cuda_bf16.h>
#include <math.h>
#include <stdint.h>

#define BATCH 8
#define SEQ   1024
#define DMODEL 1024
#define NHEAD 16
#define HDIM  64
#define FFDIM 4096
#define NTOK  (BATCH * SEQ)
#define NZ    (BATCH * NHEAD)

// ---------------- scratch (bf16 packed as uint32 pairs) ----------------
__device__ uint32_t g_h32   [(long)NTOK * 512];
__device__ uint32_t g_qb    [(long)NZ * SEQ * 32];
__device__ uint32_t g_kb    [(long)NZ * SEQ * 32];
__device__ uint32_t g_vb    [(long)NZ * SEQ * 32];
__device__ uint32_t g_vt    [(long)NZ * 64 * 512];
__device__ uint32_t g_ctxb  [(long)NTOK * 512];
__device__ float    g_attnout[(long)NTOK * DMODEL];
__device__ uint32_t g_h2b   [(long)NTOK * 512];
__device__ uint32_t g_ff1b  [(long)NTOK * 2048];
__device__ uint32_t g_wqkvb [3L * 1024 * 512];
__device__ uint32_t g_wprojb[1024L * 512];
__device__ uint32_t g_w1b   [4096L * 512];
__device__ uint32_t g_w2b   [1024L * 2048];

// ---------------- helpers ----------------
__device__ __forceinline__ uint32_t packbf(float lo, float hi) {
    __nv_bfloat162 v = __float22bfloat162_rn(make_float2(lo, hi));
    return *reinterpret_cast<uint32_t*>(&v);
}
__device__ __forceinline__ void mma_bf16(float c[4], const uint32_t a[4],
                                         uint32_t b0, uint32_t b1) {
    asm volatile(
        "mma.sync.aligned.m16n8k16.row.col.f32.bf16.bf16.f32 "
        "{%0,%1,%2,%3}, {%4,%5,%6,%7}, {%8,%9}, {%0,%1,%2,%3};\n"
        : "+f"(c[0]), "+f"(c[1]), "+f"(c[2]), "+f"(c[3])
        : "r"(a[0]), "r"(a[1]), "r"(a[2]), "r"(a[3]), "r"(b0), "r"(b1));
}
__device__ __forceinline__ void cp16(uint32_t saddr, const void* g) {
    asm volatile("cp.async.ca.shared.global [%0], [%1], 16;\n" :: "r"(saddr), "l"(g));
}
#define CP_COMMIT() asm volatile("cp.async.commit_group;\n" ::: "memory")
#define CP_WAIT(N)  asm volatile("cp.async.wait_group %0;\n" :: "n"(N) : "memory")

__device__ __forceinline__ float gelu_exact(float v) {
    return 0.5f * v * (1.0f + erff(v * 0.70710678118654752f));
}

// ---------------- fp32 -> packed bf16 convert ----------------
__global__ void cvt_bf16_kernel(const float4* __restrict__ src, uint2* __restrict__ dst, int n4) {
    int i = blockIdx.x * blockDim.x + threadIdx.x;
    if (i < n4) {
        float4 v = src[i];
        dst[i] = make_uint2(packbf(v.x, v.y), packbf(v.z, v.w));
    }
}

// ---------------- block reduce ----------------
__device__ __forceinline__ float blockReduceSum(float v, float* sbuf) {
    #pragma unroll
    for (int o = 16; o > 0; o >>= 1) v += __shfl_xor_sync(0xffffffffu, v, o);
    const int w = threadIdx.x >> 5;
    if ((threadIdx.x & 31) == 0) sbuf[w] = v;
    __syncthreads();
    if (threadIdx.x < 32) {
        float t = (threadIdx.x < 8) ? sbuf[threadIdx.x] : 0.0f;
        #pragma unroll
        for (int o = 4; o > 0; o >>= 1) t += __shfl_xor_sync(0xffffffffu, t, o);
        if (threadIdx.x == 0) sbuf[0] = t;
    }
    __syncthreads();
    float r = sbuf[0];
    __syncthreads();
    return r;
}

// ---------------- layernorm: fp32 in, packed bf16 out ----------------
__global__ void layernorm_bf16_kernel(const float* __restrict__ x, const float* __restrict__ g,
                                      const float* __restrict__ b, uint32_t* __restrict__ out) {
    __shared__ float sbuf[8];
    const long row = blockIdx.x;
    const int tid = threadIdx.x;
    const float4 xv = reinterpret_cast<const float4*>(x + row * DMODEL)[tid];
    float s = xv.x + xv.y + xv.z + xv.w;
    s = blockReduceSum(s, sbuf);
    const float mu = s * (1.0f / 1024.0f);
    const float dx = xv.x - mu, dy = xv.y - mu, dz = xv.z - mu, dw = xv.w - mu;
    float vs = dx*dx + dy*dy + dz*dz + dw*dw;
    vs = blockReduceSum(vs, sbuf);
    const float inv = rsqrtf(vs * (1.0f / 1024.0f) + 1e-5f);
    const float4 gv = reinterpret_cast<const float4*>(g)[tid];
    const float4 bv = reinterpret_cast<const float4*>(b)[tid];
    reinterpret_cast<uint2*>(out + row * 512)[tid] =
        make_uint2(packbf(dx * inv * gv.x + bv.x, dy * inv * gv.y + bv.y),
                   packbf(dz * inv * gv.z + bv.z, dw * inv * gv.w + bv.w));
}

// ---------------- bf16 GEMM: C = A @ B^T, cp.async 3-stage ----------------
// A:[M,K] packed pairs (ldap u32/row), B:[N,K] packed (ldbp).
// MODE 0: fp32 out (+fp32 res). MODE 1: packed bf16 out. MODE 2: qkv head routing.
template<int MODE, bool HAS_BIAS, bool GELU, bool HAS_RES>
__global__ void __launch_bounds__(256)
gemm_tc(const uint32_t* __restrict__ A, const uint32_t* __restrict__ B,
        const float* __restrict__ bias, const float* __restrict__ res,
        float* __restrict__ outf, uint32_t* __restrict__ outb,
        uint32_t* __restrict__ qb, uint32_t* __restrict__ kb, uint32_t* __restrict__ vb,
        int K, int ldap, int ldbp, int ldo)
{
    constexpr int LDK = 36;
    constexpr int TS = 128 * LDK;
    extern __shared__ uint32_t sm[];
    uint32_t* Asm = sm;
    uint32_t* Bsm = sm + 3 * TS;

    const int tid = threadIdx.x;
    const int lane = tid & 31;
    const int warp = tid >> 5;
    const int g = lane >> 2, t = lane & 3;
    const int m0 = (warp & 1) * 64;
    const int n0 = (warp >> 1) * 32;
    const int row0 = blockIdx.y * 128;
    const int col0 = blockIdx.x * 128;

    const uint32_t smA = (uint32_t)__cvta_generic_to_shared(Asm);
    const uint32_t smB = (uint32_t)__cvta_generic_to_shared(Bsm);

    float acc[4][4][4];
    #pragma unroll
    for (int mi = 0; mi < 4; mi++)
        #pragma unroll
        for (int ni = 0; ni < 4; ni++)
            #pragma unroll
            for (int q = 0; q < 4; q++) acc[mi][ni][q] = 0.0f;

    const int r_st = tid >> 3;
    const int k_st = tid & 7;

    auto stage = [&](int s, int buf) {
        #pragma unroll
        for (int p = 0; p < 4; p++) {
            const int r = p * 32 + r_st;
            cp16(smA + (buf * TS + r * LDK + k_st * 4) * 4,
                 A + (long)(row0 + r) * ldap + s * 32 + k_st * 4);
            cp16(smB + (buf * TS + r * LDK + k_st * 4) * 4,
                 B + (long)(col0 + r) * ldbp + s * 32 + k_st * 4);
        }
    };

    const int nt = K >> 6;
    stage(0, 0); CP_COMMIT();
    stage(1, 1); CP_COMMIT();

    for (int it = 0; it < nt; it++) {
        CP_WAIT(1);
        __syncthreads();
        if (it + 2 < nt) stage(it + 2, (it + 2) % 3);
        CP_COMMIT();
        const uint32_t* As_ = Asm + (it % 3) * TS;
        const uint32_t* Bs_ = Bsm + (it % 3) * TS;
        #pragma unroll
        for (int ks = 0; ks < 4; ks++) {
            uint32_t af[4][4], bfr[4][2];
            #pragma unroll
            for (int mi = 0; mi < 4; mi++) {
                const int mb = m0 + mi * 16 + g;
                af[mi][0] = As_[mb * LDK + 8 * ks + t];
                af[mi][1] = As_[(mb + 8) * LDK + 8 * ks + t];
                af[mi][2] = As_[mb * LDK + 8 * ks + t + 4];
                af[mi][3] = As_[(mb + 8) * LDK + 8 * ks + t + 4];
            }
            #pragma unroll
            for (int ni = 0; ni < 4; ni++) {
                const int nb = n0 + ni * 8 + g;
                bfr[ni][0] = Bs_[nb * LDK + 8 * ks + t];
                bfr[ni][1] = Bs_[nb * LDK + 8 * ks + t + 4];
            }
            #pragma unroll
            for (int mi = 0; mi < 4; mi++)
                #pragma unroll
                for (int ni = 0; ni < 4; ni++)
                    mma_bf16(acc[mi][ni], af[mi], bfr[ni][0], bfr[ni][1]);
        }
    }

    #pragma unroll
    for (int mi = 0; mi < 4; mi++) {
        #pragma unroll
        for (int ni = 0; ni < 4; ni++) {
            const int c = col0 + n0 + ni * 8 + 2 * t;
            #pragma unroll
            for (int half = 0; half < 2; half++) {
                const int r = row0 + m0 + mi * 16 + g + half * 8;
                float v0 = acc[mi][ni][half * 2 + 0];
                float v1 = acc[mi][ni][half * 2 + 1];
                if (HAS_BIAS) { v0 += bias[c]; v1 += bias[c + 1]; }
                if (GELU)     { v0 = gelu_exact(v0); v1 = gelu_exact(v1); }
                if (MODE == 0) {
                    if (HAS_RES) {
                        const float2 rv = *reinterpret_cast<const float2*>(res + (long)r * ldo + c);
                        v0 += rv.x; v1 += rv.y;
                    }
                    float2 o; o.x = v0; o.y = v1;
                    *reinterpret_cast<float2*>(outf + (long)r * ldo + c) = o;
                } else if (MODE == 1) {
                    outb[(long)r * (ldo >> 1) + (c >> 1)] = packbf(v0, v1);
                } else {
                    const int kind = c >> 10;
                    const int cc = c & 1023;
                    const int hh = cc >> 6, d = cc & 63;
                    const int bb = r >> 10, n = r & 1023;
                    const long addr = ((long)(bb * 16 + hh) * 1024 + n) * 32 + (d >> 1);
                    if (kind == 0)      qb[addr] = packbf(v0 * 0.125f, v1 * 0.125f);
                    else if (kind == 1) kb[addr] = packbf(v0, v1);
                    else                vb[addr] = packbf(v0, v1);
                }
            }
        }
    }
}

// ---------------- V transpose: Vb[z][n][d] -> Vt[z][d][kvpair packed] ----------------
__global__ void vtrans_kernel(const uint32_t* __restrict__ Vb, uint32_t* __restrict__ Vt) {
    __shared__ uint32_t Ls[128 * 35];
    const int z = blockIdx.y;
    const int tile = blockIdx.x;
    const int tid = threadIdx.x;
    const uint32_t* src = Vb + ((long)z * 1024 + tile * 128) * 32;
    #pragma unroll
    for (int j = 0; j < 16; j++) {
        const int idx = j * 256 + tid;
        const int r = idx >> 5, dw = idx & 31;
        Ls[r * 35 + dw] = src[(long)r * 32 + dw];
    }
    __syncthreads();
    #pragma unroll
    for (int j = 0; j < 16; j++) {
        const int item = j * 256 + tid;
        const int d = item >> 6, p = item & 63;
        const uint32_t lo = Ls[(2 * p) * 35 + (d >> 1)];
        const uint32_t hi = Ls[(2 * p + 1) * 35 + (d >> 1)];
        const int sh = (d & 1) * 16;
        const uint32_t v = (((hi >> sh) & 0xffffu) << 16) | ((lo >> sh) & 0xffffu);
        Vt[((long)z * 64 + d) * 512 + tile * 64 + p] = v;
    }
}

// ---------------- fused flash attention ----------------
__global__ void __launch_bounds__(256)
flash_kernel(const uint32_t* __restrict__ Qb, const uint32_t* __restrict__ Kb,
             const uint32_t* __restrict__ Vt, uint32_t* __restrict__ ctxb)
{
    constexpr int KTS = 128 * 36;
    constexpr int VTS = 64 * 68;
    extern __shared__ uint32_t sm[];
    uint32_t* Ksm = sm;
    uint32_t* Vsm = sm + 2 * KTS;

    const int z = blockIdx.y;
    const int qt = blockIdx.x;
    const int tid = threadIdx.x;
    const int lane = tid & 31;
    const int warp = tid >> 5;
    const int g = lane >> 2, t = lane & 3;

    const uint32_t* Qz = Qb + (long)z * (1024 * 32);
    const uint32_t* Kz = Kb + (long)z * (1024 * 32);
    const uint32_t* Vz = Vt + (long)z * (64 * 512);

    const uint32_t smK = (uint32_t)__cvta_generic_to_shared(Ksm);
    const uint32_t smV = (uint32_t)__cvta_generic_to_shared(Vsm);

    const int qrow = qt * 128 + warp * 16;
    uint32_t qa[4][4];
    #pragma unroll
    for (int ks = 0; ks < 4; ks++) {
        qa[ks][0] = Qz[(qrow + g) * 32 + 8 * ks + t];
        qa[ks][1] = Qz[(qrow + g + 8) * 32 + 8 * ks + t];
        qa[ks][2] = Qz[(qrow + g) * 32 + 8 * ks + t + 4];
        qa[ks][3] = Qz[(qrow + g + 8) * 32 + 8 * ks + t + 4];
    }

    float oacc[8][4];
    #pragma unroll
    for (int ni = 0; ni < 8; ni++)
        #pragma unroll
        for (int q = 0; q < 4; q++) oacc[ni][q] = 0.0f;
    float m0 = -1e30f, m1 = -1e30f, l0 = 0.0f, l1 = 0.0f;

    auto stage = [&](int c, int buf) {
        {
            const int r = tid >> 3, kb16 = tid & 7;
            #pragma unroll
            for (int p = 0; p < 4; p++)
                cp16(smK + (buf * KTS + (p * 32 + r) * 36 + kb16 * 4) * 4,
                     Kz + (long)(c * 128 + p * 32 + r) * 32 + kb16 * 4);
        }
        {
            const int d = tid >> 4, p4 = tid & 15;
            #pragma unroll
            for (int p = 0; p < 4; p++)
                cp16(smV + (buf * VTS + (p * 16 + d) * 68 + p4 * 4) * 4,
                     Vz + (long)(p * 16 + d) * 512 + c * 64 + p4 * 4);
        }
    };

    stage(0, 0); CP_COMMIT();

    for (int c = 0; c < 8; c++) {
        CP_WAIT(0);
        __syncthreads();
        if (c + 1 < 8) { stage(c + 1, (c + 1) & 1); }
        CP_COMMIT();
        const uint32_t* Ks_ = Ksm + (c & 1) * KTS;
        const uint32_t* Vs_ = Vsm + (c & 1) * VTS;

        float sacc[16][4];
        #pragma unroll
        for (int ni = 0; ni < 16; ni++)
            #pragma unroll
            for (int q = 0; q < 4; q++) sacc[ni][q] = 0.0f;
        #pragma unroll
        for (int ks = 0; ks < 4; ks++)
            #pragma unroll
            for (int ni = 0; ni < 16; ni++) {
                const int nb = ni * 8 + g;
                mma_bf16(sacc[ni], qa[ks],
                         Ks_[nb * 36 + 8 * ks + t], Ks_[nb * 36 + 8 * ks + t + 4]);
            }

        float cm0 = -1e30f, cm1 = -1e30f;
        #pragma unroll
        for (int ni = 0; ni < 16; ni++) {
            cm0 = fmaxf(cm0, fmaxf(sacc[ni][0], sacc[ni][1]));
            cm1 = fmaxf(cm1, fmaxf(sacc[ni][2], sacc[ni][3]));
        }
        cm0 = fmaxf(cm0, __shfl_xor_sync(0xffffffffu, cm0, 1));
        cm0 = fmaxf(cm0, __shfl_xor_sync(0xffffffffu, cm0, 2));
        cm1 = fmaxf(cm1, __shfl_xor_sync(0xffffffffu, cm1, 1));
        cm1 = fmaxf(cm1, __shfl_xor_sync(0xffffffffu, cm1, 2));
        const float nm0 = fmaxf(m0, cm0), nm1 = fmaxf(m1, cm1);
        const float a0 = __expf(m0 - nm0), a1 = __expf(m1 - nm1);
        #pragma unroll
        for (int ni = 0; ni < 8; ni++) {
            oacc[ni][0] *= a0; oacc[ni][1] *= a0;
            oacc[ni][2] *= a1; oacc[ni][3] *= a1;
        }
        float s0 = 0.0f, s1 = 0.0f;
        #pragma unroll
        for (int ni = 0; ni < 16; ni++) {
            sacc[ni][0] = __expf(sacc[ni][0] - nm0);
            sacc[ni][1] = __expf(sacc[ni][1] - nm0);
            sacc[ni][2] = __expf(sacc[ni][2] - nm1);
            sacc[ni][3] = __expf(sacc[ni][3] - nm1);
            s0 += sacc[ni][0] + sacc[ni][1];
            s1 += sacc[ni][2] + sacc[ni][3];
        }
        s0 += __shfl_xor_sync(0xffffffffu, s0, 1);
        s0 += __shfl_xor_sync(0xffffffffu, s0, 2);
        s1 += __shfl_xor_sync(0xffffffffu, s1, 1);
        s1 += __shfl_xor_sync(0xffffffffu, s1, 2);
        l0 = l0 * a0 + s0;
        l1 = l1 * a1 + s1;
        m0 = nm0; m1 = nm1;

        uint32_t pa[8][4];
        #pragma unroll
        for (int k2 = 0; k2 < 8; k2++) {
            pa[k2][0] = packbf(sacc[2 * k2][0],     sacc[2 * k2][1]);
            pa[k2][1] = packbf(sacc[2 * k2][2],     sacc[2 * k2][3]);
            pa[k2][2] = packbf(sacc[2 * k2 + 1][0], sacc[2 * k2 + 1][1]);
            pa[k2][3] = packbf(sacc[2 * k2 + 1][2], sacc[2 * k2 + 1][3]);
        }

        #pragma unroll
        for (int k2 = 0; k2 < 8; k2++)
            #pragma unroll
            for (int ni = 0; ni < 8; ni++) {
                const int nb = ni * 8 + g;
                mma_bf16(oacc[ni], pa[k2],
                         Vs_[nb * 68 + 8 * k2 + t], Vs_[nb * 68 + 8 * k2 + t + 4]);
            }
    }

    const float inv0 = 1.0f / l0, inv1 = 1.0f / l1;
    const int b = z >> 4, h = z & 15;
    const long token0 = (long)b * 1024 + qrow + g;
    #pragma unroll
    for (int ni = 0; ni < 8; ni++) {
        const int pairc = h * 32 + ni * 4 + t;
        ctxb[token0 * 512 + pairc]       = packbf(oacc[ni][0] * inv0, oacc[ni][1] * inv0);
        ctxb[(token0 + 8) * 512 + pairc] = packbf(oacc[ni][2] * inv1, oacc[ni][3] * inv1);
    }
}

// ---------------- host launcher ----------------
extern "C" void kernel_launch(void* const* d_in, const int* in_sizes, int n_in,
                              void* d_out, int out_size) {
    const float* x      = (const float*)d_in[0];
    const float* ln1_g  = (const float*)d_in[1];
    const float* ln1_b  = (const float*)d_in[2];
    const float* ln2_g  = (const float*)d_in[3];
    const float* ln2_b  = (const float*)d_in[4];
    const float* W_qkv  = (const float*)d_in[5];
    const float* b_qkv  = (const float*)d_in[6];
    const float* W_proj = (const float*)d_in[7];
    const float* b_proj = (const float*)d_in[8];
    const float* W1     = (const float*)d_in[9];
    const float* b1     = (const float*)d_in[10];
    const float* W2     = (const float*)d_in[11];
    const float* b2     = (const float*)d_in[12];
    float* out = (float*)d_out;

    uint32_t *h32, *qb, *kb, *vb, *vt, *ctxb, *h2b, *ff1b, *wqkvb, *wprojb, *w1b, *w2b;
    float* attnout;
    cudaGetSymbolAddress((void**)&h32,    g_h32);
    cudaGetSymbolAddress((void**)&qb,     g_qb);
    cudaGetSymbolAddress((void**)&kb,     g_kb);
    cudaGetSymbolAddress((void**)&vb,     g_vb);
    cudaGetSymbolAddress((void**)&vt,     g_vt);
    cudaGetSymbolAddress((void**)&ctxb,   g_ctxb);
    cudaGetSymbolAddress((void**)&attnout,g_attnout);
    cudaGetSymbolAddress((void**)&h2b,    g_h2b);
    cudaGetSymbolAddress((void**)&ff1b,   g_ff1b);
    cudaGetSymbolAddress((void**)&wqkvb,  g_wqkvb);
    cudaGetSymbolAddress((void**)&wprojb, g_wprojb);
    cudaGetSymbolAddress((void**)&w1b,    g_w1b);
    cudaGetSymbolAddress((void**)&w2b,    g_w2b);

    const int GEMM_SMEM  = 3 * (128 * 36) * 2 * 4;   // 110592 B
    const int FLASH_SMEM = (2 * 128 * 36 + 2 * 64 * 68) * 4;  // 71680 B
    cudaFuncSetAttribute(gemm_tc<2, true, false, false>, cudaFuncAttributeMaxDynamicSharedMemorySize, GEMM_SMEM);
    cudaFuncSetAttribute(gemm_tc<0, true, false, true>,  cudaFuncAttributeMaxDynamicSharedMemorySize, GEMM_SMEM);
    cudaFuncSetAttribute(gemm_tc<1, true, true, false>,  cudaFuncAttributeMaxDynamicSharedMemorySize, GEMM_SMEM);
    cudaFuncSetAttribute(gemm_tc<0, true, true, true>,   cudaFuncAttributeMaxDynamicSharedMemorySize, GEMM_SMEM);
    cudaFuncSetAttribute(flash_kernel, cudaFuncAttributeMaxDynamicSharedMemorySize, FLASH_SMEM);

    // 0. weight conversions (fp32 -> packed bf16)
    cvt_bf16_kernel<<<(3 * 1024 * 1024 / 4 + 255) / 256, 256>>>((const float4*)W_qkv,  (uint2*)wqkvb,  3 * 1024 * 1024 / 4);
    cvt_bf16_kernel<<<(1024 * 1024 / 4 + 255) / 256, 256>>>((const float4*)W_proj, (uint2*)wprojb, 1024 * 1024 / 4);
    cvt_bf16_kernel<<<(4096 * 1024 / 4 + 255) / 256, 256>>>((const float4*)W1,     (uint2*)w1b,    4096 * 1024 / 4);
    cvt_bf16_kernel<<<(4096 * 1024 / 4 + 255) / 256, 256>>>((const float4*)W2,     (uint2*)w2b,    4096 * 1024 / 4);

    // 1. LN1 -> bf16
    layernorm_bf16_kernel<<<NTOK, 256>>>(x, ln1_g, ln1_b, h32);

    // 2. qkv GEMM with head routing (M=8192, N=3072, K=1024)
    gemm_tc<2, true, false, false><<<dim3(24, 64), 256, GEMM_SMEM>>>(
        h32, wqkvb, b_qkv, nullptr, nullptr, nullptr, qb, kb, vb,
        1024, 512, 512, 3072);

    // 3. V transpose
    vtrans_kernel<<<dim3(8, NZ), 256>>>(vb, vt);

    // 4. fused flash attention -> ctx bf16
    flash_kernel<<<dim3(8, NZ), 256, FLASH_SMEM>>>(qb, kb, vt, ctxb);

    // 5. attnout = ctx @ Wproj^T + b + x   (fp32)
    gemm_tc<0, true, false, true><<<dim3(8, 64), 256, GEMM_SMEM>>>(
        ctxb, wprojb, b_proj, x, attnout, nullptr, nullptr, nullptr, nullptr,
        1024, 512, 512, 1024);

    // 6. LN2 -> bf16
    layernorm_bf16_kernel<<<NTOK, 256>>>(attnout, ln2_g, ln2_b, h2b);

    // 7. ff1 = gelu(h2 @ W1^T + b1) -> bf16  (N=4096)
    gemm_tc<1, true, true, false><<<dim3(32, 64), 256, GEMM_SMEM>>>(
        h2b, w1b, b1, nullptr, nullptr, ff1b, nullptr, nullptr, nullptr,
        1024, 512, 512, 4096);

    // 8. out = gelu(ff1 @ W2^T + b2) + attnout  (fp32, K=4096)
    gemm_tc<0, true, true, true><<<dim3(8, 64), 256, GEMM_SMEM>>>(
        ff1b, w2b, b2, attnout, out, nullptr, nullptr, nullptr, nullptr,
        4096, 2048, 2048, 1024);
}

// round 7
// speedup vs baseline: 7.3352x; 1.0224x over previous
#include <cuda_runtime.h>
#include <cuda_bf16.h>
#include <math.h>
#include <stdint.h>

#define BATCH 8
#define SEQ   1024
#define DMODEL 1024
#define NHEAD 16
#define HDIM  64
#define FFDIM 4096
#define NTOK  (BATCH * SEQ)
#define NZ    (BATCH * NHEAD)

// ---------------- scratch (bf16 packed as uint32 pairs) ----------------
__device__ uint32_t g_h32   [(long)NTOK * 512];
__device__ uint32_t g_qb    [(long)NZ * SEQ * 32];
__device__ uint32_t g_kb    [(long)NZ * SEQ * 32];
__device__ uint32_t g_vb    [(long)NZ * SEQ * 32];
__device__ uint32_t g_vt    [(long)NZ * 64 * 512];
__device__ uint32_t g_ctxb  [(long)NTOK * 512];
__device__ float    g_attnout[(long)NTOK * DMODEL];
__device__ uint32_t g_h2b   [(long)NTOK * 512];
__device__ uint32_t g_ff1b  [(long)NTOK * 2048];
__device__ uint32_t g_wqkvb [3L * 1024 * 512];
__device__ uint32_t g_wprojb[1024L * 512];
__device__ uint32_t g_w1b   [4096L * 512];
__device__ uint32_t g_w2b   [1024L * 2048];

// ---------------- helpers ----------------
__device__ __forceinline__ uint32_t packbf(float lo, float hi) {
    __nv_bfloat162 v = __float22bfloat162_rn(make_float2(lo, hi));
    return *reinterpret_cast<uint32_t*>(&v);
}
__device__ __forceinline__ void mma_bf16(float c[4], const uint32_t a[4],
                                         uint32_t b0, uint32_t b1) {
    asm volatile(
        "mma.sync.aligned.m16n8k16.row.col.f32.bf16.bf16.f32 "
        "{%0,%1,%2,%3}, {%4,%5,%6,%7}, {%8,%9}, {%0,%1,%2,%3};\n"
        : "+f"(c[0]), "+f"(c[1]), "+f"(c[2]), "+f"(c[3])
        : "r"(a[0]), "r"(a[1]), "r"(a[2]), "r"(a[3]), "r"(b0), "r"(b1));
}
__device__ __forceinline__ void ldsm4(uint32_t r[4], uint32_t saddr) {
    asm volatile("ldmatrix.sync.aligned.m8n8.x4.shared.b16 {%0,%1,%2,%3}, [%4];"
        : "=r"(r[0]), "=r"(r[1]), "=r"(r[2]), "=r"(r[3]) : "r"(saddr));
}
__device__ __forceinline__ void cp16(uint32_t saddr, const void* g) {
    asm volatile("cp.async.ca.shared.global [%0], [%1], 16;\n" :: "r"(saddr), "l"(g));
}
#define CP_COMMIT() asm volatile("cp.async.commit_group;\n" ::: "memory")
#define CP_WAIT(N)  asm volatile("cp.async.wait_group %0;\n" :: "n"(N) : "memory")

__device__ __forceinline__ float gelu_exact(float v) {
    return 0.5f * v * (1.0f + erff(v * 0.70710678118654752f));
}

// ---------------- fp32 -> packed bf16 convert ----------------
__global__ void cvt_bf16_kernel(const float4* __restrict__ src, uint2* __restrict__ dst, int n4) {
    int i = blockIdx.x * blockDim.x + threadIdx.x;
    if (i < n4) {
        float4 v = src[i];
        dst[i] = make_uint2(packbf(v.x, v.y), packbf(v.z, v.w));
    }
}

// ---------------- block reduce ----------------
__device__ __forceinline__ float blockReduceSum(float v, float* sbuf) {
    #pragma unroll
    for (int o = 16; o > 0; o >>= 1) v += __shfl_xor_sync(0xffffffffu, v, o);
    const int w = threadIdx.x >> 5;
    if ((threadIdx.x & 31) == 0) sbuf[w] = v;
    __syncthreads();
    if (threadIdx.x < 32) {
        float t = (threadIdx.x < 8) ? sbuf[threadIdx.x] : 0.0f;
        #pragma unroll
        for (int o = 4; o > 0; o >>= 1) t += __shfl_xor_sync(0xffffffffu, t, o);
        if (threadIdx.x == 0) sbuf[0] = t;
    }
    __syncthreads();
    float r = sbuf[0];
    __syncthreads();
    return r;
}

// ---------------- layernorm: fp32 in, packed bf16 out ----------------
__global__ void layernorm_bf16_kernel(const float* __restrict__ x, const float* __restrict__ g,
                                      const float* __restrict__ b, uint32_t* __restrict__ out) {
    __shared__ float sbuf[8];
    const long row = blockIdx.x;
    const int tid = threadIdx.x;
    const float4 xv = reinterpret_cast<const float4*>(x + row * DMODEL)[tid];
    float s = xv.x + xv.y + xv.z + xv.w;
    s = blockReduceSum(s, sbuf);
    const float mu = s * (1.0f / 1024.0f);
    const float dx = xv.x - mu, dy = xv.y - mu, dz = xv.z - mu, dw = xv.w - mu;
    float vs = dx*dx + dy*dy + dz*dz + dw*dw;
    vs = blockReduceSum(vs, sbuf);
    const float inv = rsqrtf(vs * (1.0f / 1024.0f) + 1e-5f);
    const float4 gv = reinterpret_cast<const float4*>(g)[tid];
    const float4 bv = reinterpret_cast<const float4*>(b)[tid];
    reinterpret_cast<uint2*>(out + row * 512)[tid] =
        make_uint2(packbf(dx * inv * gv.x + bv.x, dy * inv * gv.y + bv.y),
                   packbf(dz * inv * gv.z + bv.z, dw * inv * gv.w + bv.w));
}

// ================= bf16 GEMM: C = A @ B^T (ldmatrix + swizzled smem) =================
// A:[M,K] bf16 packed (ldap u32/row), B:[N,K] packed (ldbp). 128x128 tile/CTA, BK=64.
// 3 stages x 32KB, XOR-swizzled 128B rows -> 96KB smem, 2 CTAs/SM.
// MODE 0: fp32 out (+fp32 res). MODE 1: packed bf16 out. MODE 2: qkv head routing.
template<int MODE, bool HAS_BIAS, bool GELU, bool HAS_RES>
__global__ void __launch_bounds__(256, 2)
gemm7(const uint32_t* __restrict__ A, const uint32_t* __restrict__ B,
      const float* __restrict__ bias, const float* __restrict__ res,
      float* __restrict__ outf, uint32_t* __restrict__ outb,
      uint32_t* __restrict__ qb, uint32_t* __restrict__ kb, uint32_t* __restrict__ vb,
      int K, int ldap, int ldbp, int ldo)
{
    extern __shared__ __align__(1024) uint8_t smraw[];
    uint32_t smem_base;
    asm("{ .reg .u64 t; cvta.to.shared.u64 t, %1; cvt.u32.u64 %0, t; }"
        : "=r"(smem_base) : "l"(smraw));

    const int tid = threadIdx.x;
    const int lane = tid & 31;
    const int warp = tid >> 5;
    const int g = lane >> 2, t = lane & 3;
    const int lrow = lane & 15, lhalf = lane >> 4;
    const int m0 = (warp & 1) * 64;
    const int n0 = (warp >> 1) * 32;
    const int row0 = blockIdx.y * 128;
    const int col0 = blockIdx.x * 128;

    float acc[4][4][4];
    #pragma unroll
    for (int mi = 0; mi < 4; mi++)
        #pragma unroll
        for (int ni = 0; ni < 4; ni++)
            #pragma unroll
            for (int q = 0; q < 4; q++) acc[mi][ni][q] = 0.0f;

    // staging: 8 x 16B per thread per stage; A chunk idx<1024, B otherwise.
    auto stage = [&](int s, int buf) {
        const uint32_t bufb = smem_base + (uint32_t)buf * 32768u;
        #pragma unroll
        for (int p = 0; p < 8; p++) {
            const int idx = p * 256 + tid;
            const int r = (idx >> 3) & 127;
            const int u = idx & 7;
            const uint32_t sa = bufb + (uint32_t)((idx >> 10) * 16384)
                              + (uint32_t)(r * 128 + ((u ^ (r & 7)) << 4));
            const uint32_t* gsrc = (idx < 1024)
                ? (A + (long)(row0 + r) * ldap + s * 32 + u * 4)
                : (B + (long)(col0 + r) * ldbp + s * 32 + u * 4);
            cp16(sa, gsrc);
        }
    };

    auto compute = [&](int buf) {
        const uint32_t Ab = smem_base + (uint32_t)buf * 32768u;
        const uint32_t Bb = Ab + 16384u;
        #pragma unroll
        for (int ks = 0; ks < 4; ks++) {
            uint32_t af[4][4];
            #pragma unroll
            for (int mi = 0; mi < 4; mi++) {
                const int mr = m0 + mi * 16 + lrow;
                const uint32_t sa = Ab + (uint32_t)(mr * 128 + ((((ks << 1) + lhalf) ^ (mr & 7)) << 4));
                ldsm4(af[mi], sa);
            }
            uint32_t bfm[2][4];
            #pragma unroll
            for (int nj = 0; nj < 2; nj++) {
                const int nr = n0 + nj * 16 + lrow;
                const uint32_t sa = Bb + (uint32_t)(nr * 128 + ((((ks << 1) + lhalf) ^ (nr & 7)) << 4));
                ldsm4(bfm[nj], sa);
            }
            #pragma unroll
            for (int mi = 0; mi < 4; mi++) {
                mma_bf16(acc[mi][0], af[mi], bfm[0][0], bfm[0][2]);
                mma_bf16(acc[mi][1], af[mi], bfm[0][1], bfm[0][3]);
                mma_bf16(acc[mi][2], af[mi], bfm[1][0], bfm[1][2]);
                mma_bf16(acc[mi][3], af[mi], bfm[1][1], bfm[1][3]);
            }
        }
    };

    const int nt = K >> 6;
    stage(0, 0); CP_COMMIT();
    stage(1, 1); CP_COMMIT();
    for (int it = 0; it < nt; it++) {
        CP_WAIT(1);
        __syncthreads();
        if (it + 2 < nt) stage(it + 2, (it + 2) % 3);
        CP_COMMIT();
        compute(it % 3);
    }

    // ---- epilogue ----
    #pragma unroll
    for (int mi = 0; mi < 4; mi++) {
        #pragma unroll
        for (int ni = 0; ni < 4; ni++) {
            const int c = col0 + n0 + ni * 8 + 2 * t;
            #pragma unroll
            for (int half = 0; half < 2; half++) {
                const int r = row0 + m0 + mi * 16 + g + half * 8;
                float v0 = acc[mi][ni][half * 2 + 0];
                float v1 = acc[mi][ni][half * 2 + 1];
                if (HAS_BIAS) { v0 += bias[c]; v1 += bias[c + 1]; }
                if (GELU)     { v0 = gelu_exact(v0); v1 = gelu_exact(v1); }
                if (MODE == 0) {
                    if (HAS_RES) {
                        const float2 rv = *reinterpret_cast<const float2*>(res + (long)r * ldo + c);
                        v0 += rv.x; v1 += rv.y;
                    }
                    float2 o; o.x = v0; o.y = v1;
                    *reinterpret_cast<float2*>(outf + (long)r * ldo + c) = o;
                } else if (MODE == 1) {
                    outb[(long)r * (ldo >> 1) + (c >> 1)] = packbf(v0, v1);
                } else {
                    const int kind = c >> 10;
                    const int cc = c & 1023;
                    const int hh = cc >> 6, d = cc & 63;
                    const int bb = r >> 10, n = r & 1023;
                    const long addr = ((long)(bb * 16 + hh) * 1024 + n) * 32 + (d >> 1);
                    if (kind == 0)      qb[addr] = packbf(v0 * 0.125f, v1 * 0.125f);
                    else if (kind == 1) kb[addr] = packbf(v0, v1);
                    else                vb[addr] = packbf(v0, v1);
                }
            }
        }
    }
}

// ---------------- V transpose: Vb[z][n][d] -> Vt[z][d][kvpair packed] ----------------
__global__ void vtrans_kernel(const uint32_t* __restrict__ Vb, uint32_t* __restrict__ Vt) {
    __shared__ uint32_t Ls[128 * 35];
    const int z = blockIdx.y;
    const int tile = blockIdx.x;
    const int tid = threadIdx.x;
    const uint32_t* src = Vb + ((long)z * 1024 + tile * 128) * 32;
    #pragma unroll
    for (int j = 0; j < 16; j++) {
        const int idx = j * 256 + tid;
        const int r = idx >> 5, dw = idx & 31;
        Ls[r * 35 + dw] = src[(long)r * 32 + dw];
    }
    __syncthreads();
    #pragma unroll
    for (int j = 0; j < 16; j++) {
        const int item = j * 256 + tid;
        const int d = item >> 6, p = item & 63;
        const uint32_t lo = Ls[(2 * p) * 35 + (d >> 1)];
        const uint32_t hi = Ls[(2 * p + 1) * 35 + (d >> 1)];
        const int sh = (d & 1) * 16;
        const uint32_t v = (((hi >> sh) & 0xffffu) << 16) | ((lo >> sh) & 0xffffu);
        Vt[((long)z * 64 + d) * 512 + tile * 64 + p] = v;
    }
}

// ---------------- fused flash attention ----------------
__global__ void __launch_bounds__(256)
flash_kernel(const uint32_t* __restrict__ Qb, const uint32_t* __restrict__ Kb,
             const uint32_t* __restrict__ Vt, uint32_t* __restrict__ ctxb)
{
    constexpr int KTS = 128 * 36;
    constexpr int VTS = 64 * 68;
    extern __shared__ uint32_t sm[];
    uint32_t* Ksm = sm;
    uint32_t* Vsm = sm + 2 * KTS;

    const int z = blockIdx.y;
    const int qt = blockIdx.x;
    const int tid = threadIdx.x;
    const int lane = tid & 31;
    const int warp = tid >> 5;
    const int g = lane >> 2, t = lane & 3;

    const uint32_t* Qz = Qb + (long)z * (1024 * 32);
    const uint32_t* Kz = Kb + (long)z * (1024 * 32);
    const uint32_t* Vz = Vt + (long)z * (64 * 512);

    const uint32_t smK = (uint32_t)__cvta_generic_to_shared(Ksm);
    const uint32_t smV = (uint32_t)__cvta_generic_to_shared(Vsm);

    const int qrow = qt * 128 + warp * 16;
    uint32_t qa[4][4];
    #pragma unroll
    for (int ks = 0; ks < 4; ks++) {
        qa[ks][0] = Qz[(qrow + g) * 32 + 8 * ks + t];
        qa[ks][1] = Qz[(qrow + g + 8) * 32 + 8 * ks + t];
        qa[ks][2] = Qz[(qrow + g) * 32 + 8 * ks + t + 4];
        qa[ks][3] = Qz[(qrow + g + 8) * 32 + 8 * ks + t + 4];
    }

    float oacc[8][4];
    #pragma unroll
    for (int ni = 0; ni < 8; ni++)
        #pragma unroll
        for (int q = 0; q < 4; q++) oacc[ni][q] = 0.0f;
    float m0 = -1e30f, m1 = -1e30f, l0 = 0.0f, l1 = 0.0f;

    auto stage = [&](int c, int buf) {
        {
            const int r = tid >> 3, kb16 = tid & 7;
            #pragma unroll
            for (int p = 0; p < 4; p++)
                cp16(smK + (buf * KTS + (p * 32 + r) * 36 + kb16 * 4) * 4,
                     Kz + (long)(c * 128 + p * 32 + r) * 32 + kb16 * 4);
        }
        {
            const int d = tid >> 4, p4 = tid & 15;
            #pragma unroll
            for (int p = 0; p < 4; p++)
                cp16(smV + (buf * VTS + (p * 16 + d) * 68 + p4 * 4) * 4,
                     Vz + (long)(p * 16 + d) * 512 + c * 64 + p4 * 4);
        }
    };

    stage(0, 0); CP_COMMIT();

    for (int c = 0; c < 8; c++) {
        CP_WAIT(0);
        __syncthreads();
        if (c + 1 < 8) { stage(c + 1, (c + 1) & 1); }
        CP_COMMIT();
        const uint32_t* Ks_ = Ksm + (c & 1) * KTS;
        const uint32_t* Vs_ = Vsm + (c & 1) * VTS;

        float sacc[16][4];
        #pragma unroll
        for (int ni = 0; ni < 16; ni++)
            #pragma unroll
            for (int q = 0; q < 4; q++) sacc[ni][q] = 0.0f;
        #pragma unroll
        for (int ks = 0; ks < 4; ks++)
            #pragma unroll
            for (int ni = 0; ni < 16; ni++) {
                const int nb = ni * 8 + g;
                mma_bf16(sacc[ni], qa[ks],
                         Ks_[nb * 36 + 8 * ks + t], Ks_[nb * 36 + 8 * ks + t + 4]);
            }

        float cm0 = -1e30f, cm1 = -1e30f;
        #pragma unroll
        for (int ni = 0; ni < 16; ni++) {
            cm0 = fmaxf(cm0, fmaxf(sacc[ni][0], sacc[ni][1]));
            cm1 = fmaxf(cm1, fmaxf(sacc[ni][2], sacc[ni][3]));
        }
        cm0 = fmaxf(cm0, __shfl_xor_sync(0xffffffffu, cm0, 1));
        cm0 = fmaxf(cm0, __shfl_xor_sync(0xffffffffu, cm0, 2));
        cm1 = fmaxf(cm1, __shfl_xor_sync(0xffffffffu, cm1, 1));
        cm1 = fmaxf(cm1, __shfl_xor_sync(0xffffffffu, cm1, 2));
        const float nm0 = fmaxf(m0, cm0), nm1 = fmaxf(m1, cm1);
        const float a0 = __expf(m0 - nm0), a1 = __expf(m1 - nm1);
        #pragma unroll
        for (int ni = 0; ni < 8; ni++) {
            oacc[ni][0] *= a0; oacc[ni][1] *= a0;
            oacc[ni][2] *= a1; oacc[ni][3] *= a1;
        }
        float s0 = 0.0f, s1 = 0.0f;
        #pragma unroll
        for (int ni = 0; ni < 16; ni++) {
            sacc[ni][0] = __expf(sacc[ni][0] - nm0);
            sacc[ni][1] = __expf(sacc[ni][1] - nm0);
            sacc[ni][2] = __expf(sacc[ni][2] - nm1);
            sacc[ni][3] = __expf(sacc[ni][3] - nm1);
            s0 += sacc[ni][0] + sacc[ni][1];
            s1 += sacc[ni][2] + sacc[ni][3];
        }
        s0 += __shfl_xor_sync(0xffffffffu, s0, 1);
        s0 += __shfl_xor_sync(0xffffffffu, s0, 2);
        s1 += __shfl_xor_sync(0xffffffffu, s1, 1);
        s1 += __shfl_xor_sync(0xffffffffu, s1, 2);
        l0 = l0 * a0 + s0;
        l1 = l1 * a1 + s1;
        m0 = nm0; m1 = nm1;

        uint32_t pa[8][4];
        #pragma unroll
        for (int k2 = 0; k2 < 8; k2++) {
            pa[k2][0] = packbf(sacc[2 * k2][0],     sacc[2 * k2][1]);
            pa[k2][1] = packbf(sacc[2 * k2][2],     sacc[2 * k2][3]);
            pa[k2][2] = packbf(sacc[2 * k2 + 1][0], sacc[2 * k2 + 1][1]);
            pa[k2][3] = packbf(sacc[2 * k2 + 1][2], sacc[2 * k2 + 1][3]);
        }

        #pragma unroll
        for (int k2 = 0; k2 < 8; k2++)
            #pragma unroll
            for (int ni = 0; ni < 8; ni++) {
                const int nb = ni * 8 + g;
                mma_bf16(oacc[ni], pa[k2],
                         Vs_[nb * 68 + 8 * k2 + t], Vs_[nb * 68 + 8 * k2 + t + 4]);
            }
    }

    const float inv0 = 1.0f / l0, inv1 = 1.0f / l1;
    const int b = z >> 4, h = z & 15;
    const long token0 = (long)b * 1024 + qrow + g;
    #pragma unroll
    for (int ni = 0; ni < 8; ni++) {
        const int pairc = h * 32 + ni * 4 + t;
        ctxb[token0 * 512 + pairc]       = packbf(oacc[ni][0] * inv0, oacc[ni][1] * inv0);
        ctxb[(token0 + 8) * 512 + pairc] = packbf(oacc[ni][2] * inv1, oacc[ni][3] * inv1);
    }
}

// ---------------- host launcher ----------------
extern "C" void kernel_launch(void* const* d_in, const int* in_sizes, int n_in,
                              void* d_out, int out_size) {
    const float* x      = (const float*)d_in[0];
    const float* ln1_g  = (const float*)d_in[1];
    const float* ln1_b  = (const float*)d_in[2];
    const float* ln2_g  = (const float*)d_in[3];
    const float* ln2_b  = (const float*)d_in[4];
    const float* W_qkv  = (const float*)d_in[5];
    const float* b_qkv  = (const float*)d_in[6];
    const float* W_proj = (const float*)d_in[7];
    const float* b_proj = (const float*)d_in[8];
    const float* W1     = (const float*)d_in[9];
    const float* b1     = (const float*)d_in[10];
    const float* W2     = (const float*)d_in[11];
    const float* b2     = (const float*)d_in[12];
    float* out = (float*)d_out;

    uint32_t *h32, *qb, *kb, *vb, *vt, *ctxb, *h2b, *ff1b, *wqkvb, *wprojb, *w1b, *w2b;
    float* attnout;
    cudaGetSymbolAddress((void**)&h32,    g_h32);
    cudaGetSymbolAddress((void**)&qb,     g_qb);
    cudaGetSymbolAddress((void**)&kb,     g_kb);
    cudaGetSymbolAddress((void**)&vb,     g_vb);
    cudaGetSymbolAddress((void**)&vt,     g_vt);
    cudaGetSymbolAddress((void**)&ctxb,   g_ctxb);
    cudaGetSymbolAddress((void**)&attnout,g_attnout);
    cudaGetSymbolAddress((void**)&h2b,    g_h2b);
    cudaGetSymbolAddress((void**)&ff1b,   g_ff1b);
    cudaGetSymbolAddress((void**)&wqkvb,  g_wqkvb);
    cudaGetSymbolAddress((void**)&wprojb, g_wprojb);
    cudaGetSymbolAddress((void**)&w1b,    g_w1b);
    cudaGetSymbolAddress((void**)&w2b,    g_w2b);

    const int GEMM_SMEM  = 3 * 32768;                          // 98304 B -> 2 CTAs/SM
    const int FLASH_SMEM = (2 * 128 * 36 + 2 * 64 * 68) * 4;   // 71680 B
    cudaFuncSetAttribute(gemm7<2, true, false, false>, cudaFuncAttributeMaxDynamicSharedMemorySize, GEMM_SMEM);
    cudaFuncSetAttribute(gemm7<0, true, false, true>,  cudaFuncAttributeMaxDynamicSharedMemorySize, GEMM_SMEM);
    cudaFuncSetAttribute(gemm7<1, true, true, false>,  cudaFuncAttributeMaxDynamicSharedMemorySize, GEMM_SMEM);
    cudaFuncSetAttribute(gemm7<0, true, true, true>,   cudaFuncAttributeMaxDynamicSharedMemorySize, GEMM_SMEM);
    cudaFuncSetAttribute(flash_kernel, cudaFuncAttributeMaxDynamicSharedMemorySize, FLASH_SMEM);

    // 0. weight conversions (fp32 -> packed bf16)
    cvt_bf16_kernel<<<(3 * 1024 * 1024 / 4 + 255) / 256, 256>>>((const float4*)W_qkv,  (uint2*)wqkvb,  3 * 1024 * 1024 / 4);
    cvt_bf16_kernel<<<(1024 * 1024 / 4 + 255) / 256, 256>>>((const float4*)W_proj, (uint2*)wprojb, 1024 * 1024 / 4);
    cvt_bf16_kernel<<<(4096 * 1024 / 4 + 255) / 256, 256>>>((const float4*)W1,     (uint2*)w1b,    4096 * 1024 / 4);
    cvt_bf16_kernel<<<(4096 * 1024 / 4 + 255) / 256, 256>>>((const float4*)W2,     (uint2*)w2b,    4096 * 1024 / 4);

    // 1. LN1 -> bf16
    layernorm_bf16_kernel<<<NTOK, 256>>>(x, ln1_g, ln1_b, h32);

    // 2. qkv GEMM with head routing (M=8192, N=3072, K=1024)
    gemm7<2, true, false, false><<<dim3(24, 64), 256, GEMM_SMEM>>>(
        h32, wqkvb, b_qkv, nullptr, nullptr, nullptr, qb, kb, vb,
        1024, 512, 512, 3072);

    // 3. V transpose
    vtrans_kernel<<<dim3(8, NZ), 256>>>(vb, vt);

    // 4. fused flash attention -> ctx bf16
    flash_kernel<<<dim3(8, NZ), 256, FLASH_SMEM>>>(qb, kb, vt, ctxb);

    // 5. attnout = ctx @ Wproj^T + b + x   (fp32)
    gemm7<0, true, false, true><<<dim3(8, 64), 256, GEMM_SMEM>>>(
        ctxb, wprojb, b_proj, x, attnout, nullptr, nullptr, nullptr, nullptr,
        1024, 512, 512, 1024);

    // 6. LN2 -> bf16
    layernorm_bf16_kernel<<<NTOK, 256>>>(attnout, ln2_g, ln2_b, h2b);

    // 7. ff1 = gelu(h2 @ W1^T + b1) -> bf16  (N=4096)
    gemm7<1, true, true, false><<<dim3(32, 64), 256, GEMM_SMEM>>>(
        h2b, w1b, b1, nullptr, nullptr, ff1b, nullptr, nullptr, nullptr,
        1024, 512, 512, 4096);

    // 8. out = gelu(ff1 @ W2^T + b2) + attnout  (fp32, K=4096)
    gemm7<0, true, true, true><<<dim3(8, 64), 256, GEMM_SMEM>>>(
        ff1b, w2b, b2, attnout, out, nullptr, nullptr, nullptr, nullptr,
        4096, 2048, 2048, 1024);
}